// round 13
// baseline (speedup 1.0000x reference)
#include <cuda_runtime.h>
#include <cuda_fp16.h>
#include <cstdint>
#include <math.h>

// Problem constants
#define PIXELS 8192      // B*H*W = 8*32*32
#define DD 512
#define FF 32
#define NN 16384
#define HWSZ 1024
#define SPLITS 8
#define CPS (NN / SPLITS)   // 2048 codes per split
#define CH2 256             // codes per double-buffered chunk
#define XH_STR 40           // x-hi staging stride in halves (80B rows)
#define DELTA 2.5e-3f       // >= 2 * fp16 hi.hi approx error bound (9.8e-4)

// Output layout (concatenated flattened outputs, float32):
#define OUT_OFF      0
#define CLOSEST_OFF  4194304
#define LOSS_OFF     4202496
#define PERP_OFF     4202497

// Scratch (no allocations allowed)
__device__ float g_xn[PIXELS * FF];       // normalized projected x, [p][32]
__device__ float g_en[NN * FF];           // normalized codebook, [n][32]
__device__ __half g_xhi[PIXELS * FF];     // fp16(xn), linear [p][32]
// g_ehi FRAGMENT-ordered: [code-group of 8][kt 0..1][lane 0..31][4 fp16]
__device__ __half g_ehi[NN * FF];
__device__ float g_pval[SPLITS * PIXELS]; // per-split approx top1
__device__ int   g_pidx[SPLITS * PIXELS]; // per-split approx top1 index
__device__ float g_p2nd[SPLITS * PIXELS]; // per-split approx top2
__device__ unsigned long long g_best[PIXELS]; // packed (ord(sim)<<32)|~idx
__device__ int   g_work[PIXELS * SPLITS]; // flagged (pixel<<3)|split
__device__ int   g_nwork;
__device__ int   g_closest[PIXELS];
__device__ int   g_hist[NN];
__device__ float g_lossp[PIXELS];

// ---------------------------------------------------------------------------
// Kernel A: 1x1 conv projection + channel L2 normalize + fp16 hi copy.
// ---------------------------------------------------------------------------
__global__ void proj_norm_kernel(const float* __restrict__ enc,
                                 const float* __restrict__ pw,
                                 const float* __restrict__ pb)
{
    extern __shared__ float sm[];
    float* Ws  = sm;                 // 32*512
    float* xsh = sm + FF * DD;       // 32*33 (padded)
    float* nrm = xsh + 32 * 33;      // 32

    int tid = threadIdx.x;

    const float4* W4 = (const float4*)pw;
    float4* Ws4 = (float4*)Ws;
#pragma unroll
    for (int i = 0; i < 16; i++) Ws4[tid + 256 * i] = W4[tid + 256 * i];
    __syncthreads();

    int lane = tid & 31;     // pixel within tile
    int fg   = tid >> 5;     // 0..7
    int f0   = fg * 4;
    int p    = blockIdx.x * 32 + lane;
    int b    = p >> 10;
    int hw   = p & 1023;

    const float* ep = enc + (size_t)b * DD * HWSZ + hw;
    const float4* w0 = (const float4*)(Ws + (size_t)(f0 + 0) * DD);
    const float4* w1 = (const float4*)(Ws + (size_t)(f0 + 1) * DD);
    const float4* w2 = (const float4*)(Ws + (size_t)(f0 + 2) * DD);
    const float4* w3 = (const float4*)(Ws + (size_t)(f0 + 3) * DD);

    float a0 = 0.f, a1 = 0.f, a2 = 0.f, a3 = 0.f;
#pragma unroll 4
    for (int q = 0; q < 128; q++) {
        float e0 = ep[(4 * q + 0) * HWSZ];
        float e1 = ep[(4 * q + 1) * HWSZ];
        float e2 = ep[(4 * q + 2) * HWSZ];
        float e3 = ep[(4 * q + 3) * HWSZ];
        float4 W0 = w0[q], W1 = w1[q], W2 = w2[q], W3 = w3[q];
        a0 += e0 * W0.x; a0 += e1 * W0.y; a0 += e2 * W0.z; a0 += e3 * W0.w;
        a1 += e0 * W1.x; a1 += e1 * W1.y; a1 += e2 * W1.z; a1 += e3 * W1.w;
        a2 += e0 * W2.x; a2 += e1 * W2.y; a2 += e2 * W2.z; a2 += e3 * W2.w;
        a3 += e0 * W3.x; a3 += e1 * W3.y; a3 += e2 * W3.z; a3 += e3 * W3.w;
    }
    a0 += pb[f0 + 0];
    a1 += pb[f0 + 1];
    a2 += pb[f0 + 2];
    a3 += pb[f0 + 3];

    xsh[lane * 33 + f0 + 0] = a0;
    xsh[lane * 33 + f0 + 1] = a1;
    xsh[lane * 33 + f0 + 2] = a2;
    xsh[lane * 33 + f0 + 3] = a3;
    __syncthreads();

    if (tid < 32) {
        float ss = 0.f;
#pragma unroll
        for (int f = 0; f < 32; f++) { float v = xsh[tid * 33 + f]; ss += v * v; }
        nrm[tid] = fmaxf(sqrtf(ss), 1e-6f);
    }
    __syncthreads();

    float nm = nrm[lane];
    float o[4] = { a0 / nm, a1 / nm, a2 / nm, a3 / nm };
    *(float4*)(g_xn + (size_t)p * FF + f0) = *(float4*)o;

    __half* xr = g_xhi + (size_t)p * FF;
#pragma unroll
    for (int k = 0; k < 4; k++)
        xr[f0 + k] = __float2half_rn(o[k]);
}

// ---------------------------------------------------------------------------
// Kernel B: codebook L2 normalize + fragment-ordered fp16 store + zero hist.
// ---------------------------------------------------------------------------
__global__ void enorm_kernel(const float* __restrict__ emb)
{
    int tid  = threadIdx.x;
    int r    = blockIdx.x * 8 + (tid >> 5);
    int lane = tid & 31;
    float v = emb[(size_t)r * 32 + lane];
    float ss = v * v;
#pragma unroll
    for (int o = 16; o; o >>= 1) ss += __shfl_xor_sync(0xffffffffu, ss, o);
    float nm = fmaxf(sqrtf(ss), 1e-6f);
    float en = v / nm;
    g_en[(size_t)r * 32 + lane] = en;

    int k  = lane;
    int kt = k >> 4;
    int kr = k & 15;
    int fl = (r & 7) * 4 + ((kr & 7) >> 1);
    int el = (kr >> 3) * 2 + (kr & 1);
    g_ehi[(size_t)(r >> 3) * 256 + kt * 128 + fl * 4 + el] = __float2half_rn(en);

    if (tid < 8) g_hist[blockIdx.x * 8 + tid] = 0;
    if (blockIdx.x == 0 && tid == 0) g_nwork = 0;
}

// ---------------------------------------------------------------------------
// mma.sync m16n8k16 row.col fp16 -> f32
// ---------------------------------------------------------------------------
__device__ __forceinline__ void mma16816h(float* c, const uint32_t* a,
                                          uint32_t b0, uint32_t b1)
{
    asm volatile(
        "mma.sync.aligned.m16n8k16.row.col.f32.f16.f16.f32 "
        "{%0,%1,%2,%3}, {%4,%5,%6,%7}, {%8,%9}, {%0,%1,%2,%3};"
        : "+f"(c[0]), "+f"(c[1]), "+f"(c[2]), "+f"(c[3])
        : "r"(a[0]), "r"(a[1]), "r"(a[2]), "r"(a[3]), "r"(b0), "r"(b1));
}

__device__ __forceinline__ uint32_t smem_u32c(const void* p) {
    uint32_t a;
    asm("{ .reg .u64 t; cvta.to.shared.u64 t, %1; cvt.u32.u64 %0, t; }"
        : "=r"(a) : "l"(p));
    return a;
}

// exact fp32 dot (true cosine sim)
__device__ __forceinline__ float dot32(int p, int code)
{
    const float4* xr = (const float4*)(g_xn + (size_t)p * 32);
    const float4* er = (const float4*)(g_en + (size_t)code * 32);
    float s = 0.f;
#pragma unroll
    for (int q = 0; q < 8; q++) {
        float4 x = __ldg(xr + q), e = __ldg(er + q);
        s += x.x * e.x; s += x.y * e.y; s += x.z * e.z; s += x.w * e.w;
    }
    return s;
}

// order-preserving float -> uint32 (monotone for all finite floats)
__device__ __forceinline__ uint32_t f2ord(float f)
{
    uint32_t b = __float_as_uint(f);
    return (b & 0x80000000u) ? ~b : (b | 0x80000000u);
}
__device__ __forceinline__ unsigned long long packvi(float v, int idx)
{
    return ((unsigned long long)f2ord(v) << 32) | (uint32_t)(~(uint32_t)idx);
}

__device__ __forceinline__ void chunk_copy_async(uint32_t dbase, const char* src, int tid)
{
#pragma unroll
    for (int j = 0; j < 4; j++) {
        uint32_t d = dbase + (tid + 256 * j) * 16;
        asm volatile("cp.async.ca.shared.global [%0], [%1], 16;"
                     :: "r"(d), "l"(src + (tid + 256 * j) * 16) : "memory");
    }
    asm volatile("cp.async.commit_group;" ::: "memory");
}

// ---------------------------------------------------------------------------
// Kernel C (single GEMM): fp16 hi.hi approx sims; per-(split,pixel) tracks
// top1 value+index (first occurrence) AND exact top2 value (w/ duplicates).
// 256 thr = 4 pixel-quarter warps x 2 code-half warps; chunk 256 codes.
// smem: [0,16K) buf0, [16K,32K) buf1, [32K,35K) merge (val/idx/2nd x 256).
// ---------------------------------------------------------------------------
__global__ void __launch_bounds__(256, 2) sims_top2_kernel()
{
    extern __shared__ __half smc[];

    int tid  = threadIdx.x;
    int wid  = tid >> 5;
    int lane = tid & 31;
    int g    = lane >> 2;
    int kq   = lane & 3;
    int cw   = wid >> 2;
    int mw   = wid & 3;
    int px0  = blockIdx.x * 128;
    int cbase = blockIdx.y * CPS;

    // stage x-hi tile + extract A fragments (held in 16 regs)
    for (int i = tid; i < 512; i += 256) {
        int r = i >> 2, q = i & 3;
        ((uint4*)(smc + r * XH_STR))[q] =
            ((const uint4*)(g_xhi + (size_t)(px0 + r) * 32))[q];
    }
    __syncthreads();
    uint32_t A[2][2][4];
#pragma unroll
    for (int kt = 0; kt < 2; kt++) {
        int k0 = kt * 16 + kq * 2;
#pragma unroll
        for (int mt = 0; mt < 2; mt++) {
            int r0 = mw * 32 + mt * 16 + g;
            A[kt][mt][0] = *(const uint32_t*)(smc + r0 * XH_STR + k0);
            A[kt][mt][1] = *(const uint32_t*)(smc + (r0 + 8) * XH_STR + k0);
            A[kt][mt][2] = *(const uint32_t*)(smc + r0 * XH_STR + k0 + 8);
            A[kt][mt][3] = *(const uint32_t*)(smc + (r0 + 8) * XH_STR + k0 + 8);
        }
    }
    __syncthreads();

    uint32_t buf_base = smem_u32c(smc);
    chunk_copy_async(buf_base, (const char*)(g_ehi + (size_t)cbase * 32), tid);

    float bv[4], b2[4];
    int   bi[4];
#pragma unroll
    for (int s = 0; s < 4; s++) { bv[s] = -3.4e38f; b2[s] = -3.4e38f; bi[s] = 0; }

    for (int ch = 0; ch < CPS; ch += CH2) {
        int cur = (ch >> 8) & 1;
        __syncthreads();
        if (ch + CH2 < CPS) {
            chunk_copy_async(buf_base + (cur ^ 1) * 16384,
                             (const char*)(g_ehi + (size_t)(cbase + ch + CH2) * 32), tid);
            asm volatile("cp.async.wait_group 1;" ::: "memory");
        } else {
            asm volatile("cp.async.wait_group 0;" ::: "memory");
        }
        __syncthreads();

        const char* ebuf = (const char*)smc + cur * 16384;

#pragma unroll
        for (int sub = 0; sub < 4; sub++) {
            const char* es = ebuf + (cw * 16 + sub * 4) * 512;

            float acc[4][2][4];
#pragma unroll
            for (int nt = 0; nt < 4; nt++)
#pragma unroll
                for (int mt = 0; mt < 2; mt++)
#pragma unroll
                    for (int c = 0; c < 4; c++) acc[nt][mt][c] = 0.f;

#pragma unroll
            for (int kt = 0; kt < 2; kt++) {
#pragma unroll
                for (int nt = 0; nt < 4; nt++) {
                    uint2 bb = *(const uint2*)(es + nt * 512 + kt * 256 + lane * 8);
                    mma16816h(acc[nt][0], A[kt][0], bb.x, bb.y);
                    mma16816h(acc[nt][1], A[kt][1], bb.x, bb.y);
                }
            }

            int cb = cbase + ch + cw * 128 + sub * 32 + kq * 2;
#pragma unroll
            for (int mt = 0; mt < 2; mt++) {
#pragma unroll
                for (int h = 0; h < 2; h++) {
                    int s = mt * 2 + h;
                    float v[8];
#pragma unroll
                    for (int j = 0; j < 8; j++)
                        v[j] = acc[j >> 1][mt][h * 2 + (j & 1)];
                    // exact top-2 of 8 (duplicates count as 2nd)
                    float a1m = fmaxf(v[0], v[1]), a1n = fminf(v[0], v[1]);
                    float b1m = fmaxf(v[2], v[3]), b1n = fminf(v[2], v[3]);
                    float c1m = fmaxf(v[4], v[5]), c1n = fminf(v[4], v[5]);
                    float d1m = fmaxf(v[6], v[7]), d1n = fminf(v[6], v[7]);
                    float e1  = fmaxf(a1m, b1m), e2 = fminf(a1m, b1m);
                    float f1  = fmaxf(c1m, d1m), f2 = fminf(c1m, d1m);
                    float m   = fmaxf(e1, f1),  ml = fminf(e1, f1);
                    float ple = (a1m >= b1m) ? a1n : b1n;
                    float plf = (c1m >= d1m) ? c1n : d1n;
                    float m2s = (e1 >= f1) ? fmaxf(e2, ple) : fmaxf(f2, plf);
                    m2s = fmaxf(m2s, ml);

                    if (m > bv[s]) {
                        b2[s] = fmaxf(bv[s], m2s);
                        bv[s] = m;
                        int idx = 0;
#pragma unroll
                        for (int j = 7; j >= 0; j--)
                            if (v[j] == m) idx = cb + (j >> 1) * 8 + (j & 1);
                        bi[s] = idx;
                    } else {
                        b2[s] = fmaxf(b2[s], m);
                    }
                }
            }
        }
    }

    // merge across the 4 kq lanes (lower index wins ties; top2 exact)
#pragma unroll
    for (int s = 0; s < 4; s++) {
#pragma unroll
        for (int o = 1; o <= 2; o <<= 1) {
            float om = __shfl_xor_sync(0xffffffffu, bv[s], o);
            int   oi = __shfl_xor_sync(0xffffffffu, bi[s], o);
            float o2 = __shfl_xor_sync(0xffffffffu, b2[s], o);
            bool ow = (om > bv[s]) || (om == bv[s] && oi < bi[s]);
            float lo = fminf(om, bv[s]);
            float w2 = ow ? o2 : b2[s];
            b2[s] = fmaxf(lo, w2);
            if (ow) { bv[s] = om; bi[s] = oi; }
        }
    }

    // merge the two code-half warps per pixel via smem
    float* sv = (float*)((char*)smc + 32768);   // [2][128]
    int*   si = (int*)(sv + 256);               // [2][128]
    float* s2 = (float*)(si + 256);             // [2][128]
    __syncthreads();
    if (kq == 0) {
#pragma unroll
        for (int s = 0; s < 4; s++) {
            int mt = s >> 1, h = s & 1;
            int pix = mw * 32 + mt * 16 + h * 8 + g;
            sv[cw * 128 + pix] = bv[s];
            si[cw * 128 + pix] = bi[s];
            s2[cw * 128 + pix] = b2[s];
        }
    }
    __syncthreads();
    if (tid < 128) {
        float v0 = sv[tid],        v1 = sv[128 + tid];
        int   i0 = si[tid],        i1 = si[128 + tid];
        float t0 = s2[tid],        t1 = s2[128 + tid];
        bool ow = (v1 > v0) || (v1 == v0 && i1 < i0);
        float lo = fminf(v0, v1);
        float w2 = ow ? t1 : t0;
        float m2 = fmaxf(lo, w2);
        if (ow) { v0 = v1; i0 = i1; }
        size_t off = (size_t)blockIdx.y * PIXELS + px0 + tid;
        g_pval[off] = v0;
        g_pidx[off] = i0;
        g_p2nd[off] = m2;
    }
}

// ---------------------------------------------------------------------------
// Kernel R: per-pixel candidate rescore + flag emission.
// ---------------------------------------------------------------------------
__global__ void reduce_cand_kernel()
{
    int p = blockIdx.x * 256 + threadIdx.x;
    float v1[SPLITS], v2[SPLITS];
    int   ix[SPLITS];
    float M = -3.4e38f;
#pragma unroll
    for (int s = 0; s < SPLITS; s++) {
        v1[s] = g_pval[s * PIXELS + p];
        ix[s] = g_pidx[s * PIXELS + p];
        v2[s] = g_p2nd[s * PIXELS + p];
        M = fmaxf(M, v1[s]);
    }
    float th = M - DELTA;

    unsigned long long best = 0ull;
#pragma unroll
    for (int s = 0; s < SPLITS; s++) {
        if (v1[s] >= th) {
            float tv = dot32(p, ix[s]);
            unsigned long long pk = packvi(tv, ix[s]);
            if (pk > best) best = pk;
        }
    }
    g_best[p] = best;

#pragma unroll
    for (int s = 0; s < SPLITS; s++) {
        if (v2[s] >= th) {
            int w = atomicAdd(&g_nwork, 1);
            g_work[w] = (p << 3) | s;
        }
    }
}

// ---------------------------------------------------------------------------
// Kernel S: warp-parallel exact scan of flagged (pixel,split) pairs.
// ---------------------------------------------------------------------------
__global__ void scan_flag_kernel()
{
    int lane = threadIdx.x & 31;
    int gw   = (blockIdx.x * blockDim.x + threadIdx.x) >> 5;
    int nwarps = (gridDim.x * blockDim.x) >> 5;
    int n = g_nwork;

    for (int it = gw; it < n; it += nwarps) {
        int e = g_work[it];
        int p = e >> 3, s = e & 7;
        int base = s * CPS;
        float bvv = -3.4e38f;
        int   bii = 0x7fffffff;
#pragma unroll 4
        for (int j = 0; j < CPS / 32; j++) {
            int code = base + j * 32 + lane;
            float tv = dot32(p, code);
            if (tv > bvv || (tv == bvv && code < bii)) { bvv = tv; bii = code; }
        }
#pragma unroll
        for (int o = 16; o; o >>= 1) {
            float ov = __shfl_xor_sync(0xffffffffu, bvv, o);
            int   oi = __shfl_xor_sync(0xffffffffu, bii, o);
            if (ov > bvv || (ov == bvv && oi < bii)) { bvv = ov; bii = oi; }
        }
        if (lane == 0)
            atomicMax(&g_best[p], packvi(bvv, bii));
    }
}

// ---------------------------------------------------------------------------
// Kernel T: combine -> closest, histogram, per-pixel loss partial.
// ---------------------------------------------------------------------------
__global__ void combine_kernel(float* __restrict__ out)
{
    int p = blockIdx.x * 256 + threadIdx.x;
    unsigned long long b = g_best[p];
    int bi = (int)(~(uint32_t)(b & 0xffffffffu));
    g_closest[p] = bi;
    out[CLOSEST_OFF + p] = (float)bi;
    atomicAdd(&g_hist[bi], 1);

    float s2 = 0.f;
    const float4* xr = (const float4*)(g_xn + (size_t)p * 32);
    const float4* er = (const float4*)(g_en + (size_t)bi * 32);
#pragma unroll
    for (int q = 0; q < 8; q++) {
        float4 x = xr[q], e = er[q];
        float d0 = x.x - e.x, d1 = x.y - e.y, d2 = x.z - e.z, d3 = x.w - e.w;
        s2 += d0 * d0; s2 += d1 * d1; s2 += d2 * d2; s2 += d3 * d3;
    }
    g_lossp[p] = s2;
}

// ---------------------------------------------------------------------------
// Kernel D: expansion GEMM: out[b,d,hw] = sum_f lat[p][f] * exp_w[d][f] + exp_b[d]
// ---------------------------------------------------------------------------
__global__ void expand_kernel(const float* __restrict__ ew,
                              const float* __restrict__ eb,
                              float* __restrict__ out)
{
    __shared__ float Wsh[64 * 32];
    __shared__ float bsh[64];
    int tid = threadIdx.x;
    int d0  = blockIdx.y * 64;

    const float4* src = (const float4*)(ew + (size_t)d0 * 32);
    float4* dst = (float4*)Wsh;
    dst[tid]       = src[tid];
    dst[tid + 256] = src[tid + 256];
    if (tid < 64) bsh[tid] = eb[d0 + tid];
    __syncthreads();

    int p  = blockIdx.x * 256 + tid;
    int b  = p >> 10;
    int hw = p & 1023;
    int idx = g_closest[p];

    float4 lat[8];
    const float4* lr = (const float4*)(g_en + (size_t)idx * 32);
#pragma unroll
    for (int q = 0; q < 8; q++) lat[q] = lr[q];

    float* outp = out + OUT_OFF + ((size_t)b * 512 + d0) * 1024 + hw;
#pragma unroll 2
    for (int dd = 0; dd < 64; dd++) {
        const float4* wr = (const float4*)(Wsh + dd * 32);
        float s = bsh[dd];
#pragma unroll
        for (int q = 0; q < 8; q++) {
            float4 w = wr[q];
            s += lat[q].x * w.x; s += lat[q].y * w.y;
            s += lat[q].z * w.z; s += lat[q].w * w.w;
        }
        outp[(size_t)dd * 1024] = s;
    }
}

// ---------------------------------------------------------------------------
// Kernel G: deterministic final reductions -> loss_q, perplexity
// ---------------------------------------------------------------------------
__global__ void finalize_kernel(float* __restrict__ out)
{
    __shared__ double sh[256];
    int tid = threadIdx.x;

    double ls = 0.0;
    for (int i = tid; i < PIXELS; i += 256) ls += (double)g_lossp[i];
    sh[tid] = ls;
    __syncthreads();
    for (int o = 128; o; o >>= 1) {
        if (tid < o) sh[tid] += sh[tid + o];
        __syncthreads();
    }
    double loss = sh[0] / (double)(PIXELS * 32);
    __syncthreads();

    double ps = 0.0;
    for (int i = tid; i < NN; i += 256) {
        float u = (float)g_hist[i] * (1.0f / 8192.0f);
        ps += -(double)u * log((double)u + 1e-6);
    }
    sh[tid] = ps;
    __syncthreads();
    for (int o = 128; o; o >>= 1) {
        if (tid < o) sh[tid] += sh[tid + o];
        __syncthreads();
    }
    if (tid == 0) {
        out[LOSS_OFF] = (float)loss;
        out[PERP_OFF] = (float)exp(sh[0]);
    }
}

// ---------------------------------------------------------------------------
extern "C" void kernel_launch(void* const* d_in, const int* in_sizes, int n_in,
                              void* d_out, int out_size)
{
    const float* enc = (const float*)d_in[0];  // [8,512,32,32]
    const float* emb = (const float*)d_in[1];  // [16384,32]
    const float* pw  = (const float*)d_in[2];  // [32,512]
    const float* pb  = (const float*)d_in[3];  // [32]
    const float* ew  = (const float*)d_in[4];  // [512,32]
    const float* eb  = (const float*)d_in[5];  // [512]
    float* out = (float*)d_out;

    (void)in_sizes; (void)n_in; (void)out_size;

    const int a_smem = (FF * DD + 32 * 33 + 32) * (int)sizeof(float); // 69888
    cudaFuncSetAttribute(proj_norm_kernel,
                         cudaFuncAttributeMaxDynamicSharedMemorySize, a_smem);

    const int c_smem = 32768 + 3072;  // 2x16KB chunk buffers + merge (v/i/2nd)
    cudaFuncSetAttribute(sims_top2_kernel,
                         cudaFuncAttributeMaxDynamicSharedMemorySize, c_smem);

    proj_norm_kernel<<<256, 256, a_smem>>>(enc, pw, pb);
    enorm_kernel<<<2048, 256>>>(emb);
    sims_top2_kernel<<<dim3(64, SPLITS), 256, c_smem>>>();
    reduce_cand_kernel<<<32, 256>>>();
    scan_flag_kernel<<<128, 256>>>();
    combine_kernel<<<32, 256>>>(out);
    expand_kernel<<<dim3(32, 8), 256>>>(ew, eb, out);
    finalize_kernel<<<1, 256>>>(out);
}

// round 14
// speedup vs baseline: 1.2793x; 1.2793x over previous
#include <cuda_runtime.h>
#include <cuda_fp16.h>
#include <cstdint>
#include <math.h>

// Problem constants
#define PIXELS 8192      // B*H*W = 8*32*32
#define DD 512
#define FF 32
#define NN 16384
#define HWSZ 1024
#define SPLITS 8
#define CPS (NN / SPLITS)   // 2048 codes per split (per blockIdx.y)
#define CH2 256             // codes per double-buffered chunk
#define XH_STR 40           // x-hi staging stride in halves (80B rows)
#define NGRAN 256           // 64-code granules over 16384 codes
#define DELTA 2.5e-3f       // >= 2 * fp16 hi.hi approx error bound

// Output layout (concatenated flattened outputs, float32):
#define OUT_OFF      0
#define CLOSEST_OFF  4194304
#define LOSS_OFF     4202496
#define PERP_OFF     4202497

// Scratch (no allocations allowed)
__device__ float g_xn[PIXELS * FF];       // normalized projected x, [p][32]
__device__ float g_en[NN * FF];           // normalized codebook, [n][32]
__device__ __half g_xhi[PIXELS * FF];     // fp16(xn), linear [p][32]
// g_ehi FRAGMENT-ordered: [code-group of 8][kt 0..1][lane 0..31][4 fp16]
__device__ __half g_ehi[NN * FF];
__device__ float g_cmax[NGRAN * PIXELS];  // approx max per (granule, pixel)
__device__ unsigned long long g_best[PIXELS]; // packed (ord(sim)<<32)|~idx
__device__ int   g_work[PIXELS * NGRAN / 8];  // flagged (pixel<<8)|granule
__device__ int   g_nwork;
__device__ int   g_hist[NN];
__device__ float g_lossp[PIXELS];

// ---------------------------------------------------------------------------
// Kernel A: 1x1 conv projection + channel L2 normalize + fp16 hi copy.
// ---------------------------------------------------------------------------
__global__ void proj_norm_kernel(const float* __restrict__ enc,
                                 const float* __restrict__ pw,
                                 const float* __restrict__ pb)
{
    extern __shared__ float sm[];
    float* Ws  = sm;                 // 32*512
    float* xsh = sm + FF * DD;       // 32*33 (padded)
    float* nrm = xsh + 32 * 33;      // 32

    int tid = threadIdx.x;

    const float4* W4 = (const float4*)pw;
    float4* Ws4 = (float4*)Ws;
#pragma unroll
    for (int i = 0; i < 16; i++) Ws4[tid + 256 * i] = W4[tid + 256 * i];
    __syncthreads();

    int lane = tid & 31;     // pixel within tile
    int fg   = tid >> 5;     // 0..7
    int f0   = fg * 4;
    int p    = blockIdx.x * 32 + lane;
    int b    = p >> 10;
    int hw   = p & 1023;

    const float* ep = enc + (size_t)b * DD * HWSZ + hw;
    const float4* w0 = (const float4*)(Ws + (size_t)(f0 + 0) * DD);
    const float4* w1 = (const float4*)(Ws + (size_t)(f0 + 1) * DD);
    const float4* w2 = (const float4*)(Ws + (size_t)(f0 + 2) * DD);
    const float4* w3 = (const float4*)(Ws + (size_t)(f0 + 3) * DD);

    float a0 = 0.f, a1 = 0.f, a2 = 0.f, a3 = 0.f;
#pragma unroll 4
    for (int q = 0; q < 128; q++) {
        float e0 = ep[(4 * q + 0) * HWSZ];
        float e1 = ep[(4 * q + 1) * HWSZ];
        float e2 = ep[(4 * q + 2) * HWSZ];
        float e3 = ep[(4 * q + 3) * HWSZ];
        float4 W0 = w0[q], W1 = w1[q], W2 = w2[q], W3 = w3[q];
        a0 += e0 * W0.x; a0 += e1 * W0.y; a0 += e2 * W0.z; a0 += e3 * W0.w;
        a1 += e0 * W1.x; a1 += e1 * W1.y; a1 += e2 * W1.z; a1 += e3 * W1.w;
        a2 += e0 * W2.x; a2 += e1 * W2.y; a2 += e2 * W2.z; a2 += e3 * W2.w;
        a3 += e0 * W3.x; a3 += e1 * W3.y; a3 += e2 * W3.z; a3 += e3 * W3.w;
    }
    a0 += pb[f0 + 0];
    a1 += pb[f0 + 1];
    a2 += pb[f0 + 2];
    a3 += pb[f0 + 3];

    xsh[lane * 33 + f0 + 0] = a0;
    xsh[lane * 33 + f0 + 1] = a1;
    xsh[lane * 33 + f0 + 2] = a2;
    xsh[lane * 33 + f0 + 3] = a3;
    __syncthreads();

    if (tid < 32) {
        float ss = 0.f;
#pragma unroll
        for (int f = 0; f < 32; f++) { float v = xsh[tid * 33 + f]; ss += v * v; }
        nrm[tid] = fmaxf(sqrtf(ss), 1e-6f);
    }
    __syncthreads();

    float nm = nrm[lane];
    float o[4] = { a0 / nm, a1 / nm, a2 / nm, a3 / nm };
    *(float4*)(g_xn + (size_t)p * FF + f0) = *(float4*)o;

    __half* xr = g_xhi + (size_t)p * FF;
#pragma unroll
    for (int k = 0; k < 4; k++)
        xr[f0 + k] = __float2half_rn(o[k]);
}

// ---------------------------------------------------------------------------
// Kernel B: codebook L2 normalize + fragment-ordered fp16 store + zero hist.
// ---------------------------------------------------------------------------
__global__ void enorm_kernel(const float* __restrict__ emb)
{
    int tid  = threadIdx.x;
    int r    = blockIdx.x * 8 + (tid >> 5);
    int lane = tid & 31;
    float v = emb[(size_t)r * 32 + lane];
    float ss = v * v;
#pragma unroll
    for (int o = 16; o; o >>= 1) ss += __shfl_xor_sync(0xffffffffu, ss, o);
    float nm = fmaxf(sqrtf(ss), 1e-6f);
    float en = v / nm;
    g_en[(size_t)r * 32 + lane] = en;

    int k  = lane;
    int kt = k >> 4;
    int kr = k & 15;
    int fl = (r & 7) * 4 + ((kr & 7) >> 1);
    int el = (kr >> 3) * 2 + (kr & 1);
    g_ehi[(size_t)(r >> 3) * 256 + kt * 128 + fl * 4 + el] = __float2half_rn(en);

    if (tid < 8) g_hist[blockIdx.x * 8 + tid] = 0;
}

// ---------------------------------------------------------------------------
// Kernel I: init g_best / g_nwork (also keeps sims in ncu launch slot 4)
// ---------------------------------------------------------------------------
__global__ void init_kernel()
{
    int p = blockIdx.x * 256 + threadIdx.x;
    g_best[p] = 0ull;
    if (p == 0) g_nwork = 0;
}

// ---------------------------------------------------------------------------
// mma.sync m16n8k16 row.col fp16 -> f32
// ---------------------------------------------------------------------------
__device__ __forceinline__ void mma16816h(float* c, const uint32_t* a,
                                          uint32_t b0, uint32_t b1)
{
    asm volatile(
        "mma.sync.aligned.m16n8k16.row.col.f32.f16.f16.f32 "
        "{%0,%1,%2,%3}, {%4,%5,%6,%7}, {%8,%9}, {%0,%1,%2,%3};"
        : "+f"(c[0]), "+f"(c[1]), "+f"(c[2]), "+f"(c[3])
        : "r"(a[0]), "r"(a[1]), "r"(a[2]), "r"(a[3]), "r"(b0), "r"(b1));
}

__device__ __forceinline__ uint32_t smem_u32c(const void* p) {
    uint32_t a;
    asm("{ .reg .u64 t; cvta.to.shared.u64 t, %1; cvt.u32.u64 %0, t; }"
        : "=r"(a) : "l"(p));
    return a;
}

// exact fp32 dot (true cosine sim)
__device__ __forceinline__ float dot32(int p, int code)
{
    const float4* xr = (const float4*)(g_xn + (size_t)p * 32);
    const float4* er = (const float4*)(g_en + (size_t)code * 32);
    float s = 0.f;
#pragma unroll
    for (int q = 0; q < 8; q++) {
        float4 x = __ldg(xr + q), e = __ldg(er + q);
        s += x.x * e.x; s += x.y * e.y; s += x.z * e.z; s += x.w * e.w;
    }
    return s;
}

// order-preserving float -> uint32 (monotone for all finite floats)
__device__ __forceinline__ uint32_t f2ord(float f)
{
    uint32_t b = __float_as_uint(f);
    return (b & 0x80000000u) ? ~b : (b | 0x80000000u);
}
__device__ __forceinline__ unsigned long long packvi(float v, int idx)
{
    return ((unsigned long long)f2ord(v) << 32) | (uint32_t)(~(uint32_t)idx);
}

__device__ __forceinline__ void chunk_copy_async(uint32_t dbase, const char* src, int tid)
{
#pragma unroll
    for (int j = 0; j < 4; j++) {
        uint32_t d = dbase + (tid + 256 * j) * 16;
        asm volatile("cp.async.ca.shared.global [%0], [%1], 16;"
                     :: "r"(d), "l"(src + (tid + 256 * j) * 16) : "memory");
    }
    asm volatile("cp.async.commit_group;" ::: "memory");
}

// ---------------------------------------------------------------------------
// Kernel C: fp16 hi.hi approx sims, per-(pixel, 64-code granule) MAX only.
// 256 thr = 4 pixel-quarter warps x 2 code-half warps; chunk 256 codes.
// Epilogue per chunk: fmax trees + 2 shfls per granule-slot + 1 store.
// smem: [0,16K) buf0, [16K,32K) buf1 (x staging overlaps buf0 pre-loop).
// ---------------------------------------------------------------------------
__global__ void __launch_bounds__(256, 2) sims_max_kernel()
{
    extern __shared__ __half smc[];

    int tid  = threadIdx.x;
    int wid  = tid >> 5;
    int lane = tid & 31;
    int g    = lane >> 2;
    int kq   = lane & 3;
    int cw   = wid >> 2;
    int mw   = wid & 3;
    int px0  = blockIdx.x * 128;
    int cbase = blockIdx.y * CPS;

    // stage x-hi tile + extract A fragments (16 regs)
    for (int i = tid; i < 512; i += 256) {
        int r = i >> 2, q = i & 3;
        ((uint4*)(smc + r * XH_STR))[q] =
            ((const uint4*)(g_xhi + (size_t)(px0 + r) * 32))[q];
    }
    __syncthreads();
    uint32_t A[2][2][4];
#pragma unroll
    for (int kt = 0; kt < 2; kt++) {
        int k0 = kt * 16 + kq * 2;
#pragma unroll
        for (int mt = 0; mt < 2; mt++) {
            int r0 = mw * 32 + mt * 16 + g;
            A[kt][mt][0] = *(const uint32_t*)(smc + r0 * XH_STR + k0);
            A[kt][mt][1] = *(const uint32_t*)(smc + (r0 + 8) * XH_STR + k0);
            A[kt][mt][2] = *(const uint32_t*)(smc + r0 * XH_STR + k0 + 8);
            A[kt][mt][3] = *(const uint32_t*)(smc + (r0 + 8) * XH_STR + k0 + 8);
        }
    }
    __syncthreads();

    // per-slot pixel ids (for cmax stores)
    int pix[4];
#pragma unroll
    for (int s = 0; s < 4; s++) {
        int mt = s >> 1, h = s & 1;
        pix[s] = px0 + mw * 32 + mt * 16 + h * 8 + g;
    }

    uint32_t buf_base = smem_u32c(smc);
    chunk_copy_async(buf_base, (const char*)(g_ehi + (size_t)cbase * 32), tid);

    for (int ch = 0; ch < CPS; ch += CH2) {
        int cur = (ch >> 8) & 1;
        __syncthreads();
        if (ch + CH2 < CPS) {
            chunk_copy_async(buf_base + (cur ^ 1) * 16384,
                             (const char*)(g_ehi + (size_t)(cbase + ch + CH2) * 32), tid);
            asm volatile("cp.async.wait_group 1;" ::: "memory");
        } else {
            asm volatile("cp.async.wait_group 0;" ::: "memory");
        }
        __syncthreads();

        const char* ebuf = (const char*)smc + cur * 16384;

        float gm[2][4];   // [64-code granule within cw half][slot]
#pragma unroll
        for (int u = 0; u < 2; u++)
#pragma unroll
            for (int s = 0; s < 4; s++) gm[u][s] = -3.4e38f;

#pragma unroll
        for (int sub = 0; sub < 4; sub++) {
            const char* es = ebuf + (cw * 16 + sub * 4) * 512;

            float acc[4][2][4];
#pragma unroll
            for (int nt = 0; nt < 4; nt++)
#pragma unroll
                for (int mt = 0; mt < 2; mt++)
#pragma unroll
                    for (int c = 0; c < 4; c++) acc[nt][mt][c] = 0.f;

#pragma unroll
            for (int kt = 0; kt < 2; kt++) {
#pragma unroll
                for (int nt = 0; nt < 4; nt++) {
                    uint2 bb = *(const uint2*)(es + nt * 512 + kt * 256 + lane * 8);
                    mma16816h(acc[nt][0], A[kt][0], bb.x, bb.y);
                    mma16816h(acc[nt][1], A[kt][1], bb.x, bb.y);
                }
            }

            int u = sub >> 1;
#pragma unroll
            for (int mt = 0; mt < 2; mt++) {
#pragma unroll
                for (int h = 0; h < 2; h++) {
                    int s = mt * 2 + h;
                    float m01 = fmaxf(acc[0][mt][h * 2], acc[0][mt][h * 2 + 1]);
                    float m23 = fmaxf(acc[1][mt][h * 2], acc[1][mt][h * 2 + 1]);
                    float m45 = fmaxf(acc[2][mt][h * 2], acc[2][mt][h * 2 + 1]);
                    float m67 = fmaxf(acc[3][mt][h * 2], acc[3][mt][h * 2 + 1]);
                    gm[u][s] = fmaxf(gm[u][s],
                                     fmaxf(fmaxf(m01, m23), fmaxf(m45, m67)));
                }
            }
        }

        // reduce each granule-slot over the 4 kq lanes and store
        int cg = (cbase + ch) >> 8;           // global 256-code chunk id
#pragma unroll
        for (int u = 0; u < 2; u++) {
#pragma unroll
            for (int s = 0; s < 4; s++) {
                float v = gm[u][s];
                v = fmaxf(v, __shfl_xor_sync(0xffffffffu, v, 1));
                v = fmaxf(v, __shfl_xor_sync(0xffffffffu, v, 2));
                if (kq == 0) {
                    int row = cg * 4 + cw * 2 + u;   // 64-code granule id
                    g_cmax[(size_t)row * PIXELS + pix[s]] = v;
                }
            }
        }
    }
}

// ---------------------------------------------------------------------------
// Kernel FL: per-pixel threshold + flag granules within DELTA of max.
// ---------------------------------------------------------------------------
__global__ void flag_kernel()
{
    int p = blockIdx.x * 256 + threadIdx.x;
    float M = -3.4e38f;
#pragma unroll 8
    for (int i = 0; i < NGRAN; i++)
        M = fmaxf(M, g_cmax[(size_t)i * PIXELS + p]);
    float th = M - DELTA;
#pragma unroll 8
    for (int i = 0; i < NGRAN; i++) {
        if (g_cmax[(size_t)i * PIXELS + p] >= th) {
            int w = atomicAdd(&g_nwork, 1);
            g_work[w] = (p << 8) | i;
        }
    }
}

// ---------------------------------------------------------------------------
// Kernel S: warp-per-granule exact fp32 rescore of flagged (pixel,granule).
// ---------------------------------------------------------------------------
__global__ void scan_kernel()
{
    int lane = threadIdx.x & 31;
    int gw   = (blockIdx.x * blockDim.x + threadIdx.x) >> 5;
    int nwarps = (gridDim.x * blockDim.x) >> 5;
    int n = g_nwork;

    for (int it = gw; it < n; it += nwarps) {
        int e = g_work[it];
        int p = e >> 8;
        int base = (e & 255) * 64;
        float bv = -3.4e38f;
        int   bi = 0x7fffffff;
#pragma unroll
        for (int j = 0; j < 2; j++) {
            int code = base + j * 32 + lane;
            float tv = dot32(p, code);
            if (tv > bv || (tv == bv && code < bi)) { bv = tv; bi = code; }
        }
#pragma unroll
        for (int o = 16; o; o >>= 1) {
            float ov = __shfl_xor_sync(0xffffffffu, bv, o);
            int   oi = __shfl_xor_sync(0xffffffffu, bi, o);
            if (ov > bv || (ov == bv && oi < bi)) { bv = ov; bi = oi; }
        }
        if (lane == 0)
            atomicMax(&g_best[p], packvi(bv, bi));
    }
}

// ---------------------------------------------------------------------------
// Kernel D: expansion GEMM + fused combine (closest/hist/loss on y==0).
// ---------------------------------------------------------------------------
__global__ void expand_kernel(const float* __restrict__ ew,
                              const float* __restrict__ eb,
                              float* __restrict__ out)
{
    __shared__ float Wsh[64 * 32];
    __shared__ float bsh[64];
    int tid = threadIdx.x;
    int d0  = blockIdx.y * 64;

    const float4* src = (const float4*)(ew + (size_t)d0 * 32);
    float4* dst = (float4*)Wsh;
    dst[tid]       = src[tid];
    dst[tid + 256] = src[tid + 256];
    if (tid < 64) bsh[tid] = eb[d0 + tid];
    __syncthreads();

    int p  = blockIdx.x * 256 + tid;
    int b  = p >> 10;
    int hw = p & 1023;
    unsigned long long bb = g_best[p];
    int idx = (int)(~(uint32_t)(bb & 0xffffffffu));

    float4 lat[8];
    const float4* lr = (const float4*)(g_en + (size_t)idx * 32);
#pragma unroll
    for (int q = 0; q < 8; q++) lat[q] = lr[q];

    if (blockIdx.y == 0) {
        out[CLOSEST_OFF + p] = (float)idx;
        atomicAdd(&g_hist[idx], 1);
        float s2 = 0.f;
        const float4* xr = (const float4*)(g_xn + (size_t)p * 32);
#pragma unroll
        for (int q = 0; q < 8; q++) {
            float4 x = xr[q];
            float d0_ = x.x - lat[q].x, d1 = x.y - lat[q].y;
            float d2 = x.z - lat[q].z, d3 = x.w - lat[q].w;
            s2 += d0_ * d0_; s2 += d1 * d1; s2 += d2 * d2; s2 += d3 * d3;
        }
        g_lossp[p] = s2;
    }

    float* outp = out + OUT_OFF + ((size_t)b * 512 + d0) * 1024 + hw;
#pragma unroll 2
    for (int dd = 0; dd < 64; dd++) {
        const float4* wr = (const float4*)(Wsh + dd * 32);
        float s = bsh[dd];
#pragma unroll
        for (int q = 0; q < 8; q++) {
            float4 w = wr[q];
            s += lat[q].x * w.x; s += lat[q].y * w.y;
            s += lat[q].z * w.z; s += lat[q].w * w.w;
        }
        outp[(size_t)dd * 1024] = s;
    }
}

// ---------------------------------------------------------------------------
// Kernel G: deterministic final reductions -> loss_q, perplexity
// ---------------------------------------------------------------------------
__global__ void finalize_kernel(float* __restrict__ out)
{
    __shared__ double sh[256];
    int tid = threadIdx.x;

    double ls = 0.0;
    for (int i = tid; i < PIXELS; i += 256) ls += (double)g_lossp[i];
    sh[tid] = ls;
    __syncthreads();
    for (int o = 128; o; o >>= 1) {
        if (tid < o) sh[tid] += sh[tid + o];
        __syncthreads();
    }
    double loss = sh[0] / (double)(PIXELS * 32);
    __syncthreads();

    double ps = 0.0;
    for (int i = tid; i < NN; i += 256) {
        float u = (float)g_hist[i] * (1.0f / 8192.0f);
        ps += (double)(-u * logf(u + 1e-6f));
    }
    sh[tid] = ps;
    __syncthreads();
    for (int o = 128; o; o >>= 1) {
        if (tid < o) sh[tid] += sh[tid + o];
        __syncthreads();
    }
    if (tid == 0) {
        out[LOSS_OFF] = (float)loss;
        out[PERP_OFF] = expf((float)sh[0]);
    }
}

// ---------------------------------------------------------------------------
extern "C" void kernel_launch(void* const* d_in, const int* in_sizes, int n_in,
                              void* d_out, int out_size)
{
    const float* enc = (const float*)d_in[0];  // [8,512,32,32]
    const float* emb = (const float*)d_in[1];  // [16384,32]
    const float* pw  = (const float*)d_in[2];  // [32,512]
    const float* pb  = (const float*)d_in[3];  // [32]
    const float* ew  = (const float*)d_in[4];  // [512,32]
    const float* eb  = (const float*)d_in[5];  // [512]
    float* out = (float*)d_out;

    (void)in_sizes; (void)n_in; (void)out_size;

    const int a_smem = (FF * DD + 32 * 33 + 32) * (int)sizeof(float); // 69888
    cudaFuncSetAttribute(proj_norm_kernel,
                         cudaFuncAttributeMaxDynamicSharedMemorySize, a_smem);

    const int c_smem = 32768;  // 2x16KB chunk buffers (x staging overlaps)
    cudaFuncSetAttribute(sims_max_kernel,
                         cudaFuncAttributeMaxDynamicSharedMemorySize, c_smem);

    proj_norm_kernel<<<256, 256, a_smem>>>(enc, pw, pb);
    enorm_kernel<<<2048, 256>>>(emb);
    init_kernel<<<32, 256>>>();
    sims_max_kernel<<<dim3(64, SPLITS), 256, c_smem>>>();
    flag_kernel<<<32, 256>>>();
    scan_kernel<<<148, 256>>>();
    expand_kernel<<<dim3(32, 8), 256>>>(ew, eb, out);
    finalize_kernel<<<1, 256>>>(out);
}

// round 15
// speedup vs baseline: 1.3105x; 1.0244x over previous
#include <cuda_runtime.h>
#include <cuda_fp16.h>
#include <cstdint>
#include <math.h>

// Problem constants
#define PIXELS 8192      // B*H*W = 8*32*32
#define DD 512
#define FF 32
#define NN 16384
#define HWSZ 1024
#define SPLITS 8
#define CPS (NN / SPLITS)   // 2048 codes per split (per blockIdx.y)
#define CH2 256             // codes per double-buffered chunk
#define XH_STR 40           // x-hi staging stride in halves (80B rows)
#define NGRAN 256           // 64-code granules over 16384 codes
#define DELTA 2.5e-3f       // >= 2 * fp16 hi.hi approx error bound

// Output layout (concatenated flattened outputs, float32):
#define OUT_OFF      0
#define CLOSEST_OFF  4194304
#define LOSS_OFF     4202496
#define PERP_OFF     4202497

// Scratch (no allocations allowed)
__device__ float g_xn[PIXELS * FF];       // normalized projected x, [p][32]
__device__ float g_en[NN * FF];           // normalized codebook, [n][32]
__device__ __half g_xhi[PIXELS * FF];     // fp16(xn), linear [p][32]
// g_ehi FRAGMENT-ordered: [code-group of 8][kt 0..1][lane 0..31][4 fp16]
__device__ __half g_ehi[NN * FF];
__device__ float g_cmax[NGRAN * PIXELS];  // approx max per (granule, pixel)
__device__ unsigned long long g_best[PIXELS]; // packed (ord(sim)<<32)|~idx
__device__ int   g_work[PIXELS * NGRAN / 8];  // flagged (pixel<<8)|granule
__device__ int   g_nwork;
__device__ int   g_hist[NN];
__device__ float g_lossp[PIXELS];

// ---------------------------------------------------------------------------
// Kernel A: 1x1 conv projection + channel L2 normalize + fp16 hi copy.
// ---------------------------------------------------------------------------
__global__ void proj_norm_kernel(const float* __restrict__ enc,
                                 const float* __restrict__ pw,
                                 const float* __restrict__ pb)
{
    extern __shared__ float sm[];
    float* Ws  = sm;                 // 32*512
    float* xsh = sm + FF * DD;       // 32*33 (padded)
    float* nrm = xsh + 32 * 33;      // 32

    int tid = threadIdx.x;

    const float4* W4 = (const float4*)pw;
    float4* Ws4 = (float4*)Ws;
#pragma unroll
    for (int i = 0; i < 16; i++) Ws4[tid + 256 * i] = W4[tid + 256 * i];
    __syncthreads();

    int lane = tid & 31;     // pixel within tile
    int fg   = tid >> 5;     // 0..7
    int f0   = fg * 4;
    int p    = blockIdx.x * 32 + lane;
    int b    = p >> 10;
    int hw   = p & 1023;

    const float* ep = enc + (size_t)b * DD * HWSZ + hw;
    const float4* w0 = (const float4*)(Ws + (size_t)(f0 + 0) * DD);
    const float4* w1 = (const float4*)(Ws + (size_t)(f0 + 1) * DD);
    const float4* w2 = (const float4*)(Ws + (size_t)(f0 + 2) * DD);
    const float4* w3 = (const float4*)(Ws + (size_t)(f0 + 3) * DD);

    float a0 = 0.f, a1 = 0.f, a2 = 0.f, a3 = 0.f;
#pragma unroll 4
    for (int q = 0; q < 128; q++) {
        float e0 = ep[(4 * q + 0) * HWSZ];
        float e1 = ep[(4 * q + 1) * HWSZ];
        float e2 = ep[(4 * q + 2) * HWSZ];
        float e3 = ep[(4 * q + 3) * HWSZ];
        float4 W0 = w0[q], W1 = w1[q], W2 = w2[q], W3 = w3[q];
        a0 += e0 * W0.x; a0 += e1 * W0.y; a0 += e2 * W0.z; a0 += e3 * W0.w;
        a1 += e0 * W1.x; a1 += e1 * W1.y; a1 += e2 * W1.z; a1 += e3 * W1.w;
        a2 += e0 * W2.x; a2 += e1 * W2.y; a2 += e2 * W2.z; a2 += e3 * W2.w;
        a3 += e0 * W3.x; a3 += e1 * W3.y; a3 += e2 * W3.z; a3 += e3 * W3.w;
    }
    a0 += pb[f0 + 0];
    a1 += pb[f0 + 1];
    a2 += pb[f0 + 2];
    a3 += pb[f0 + 3];

    xsh[lane * 33 + f0 + 0] = a0;
    xsh[lane * 33 + f0 + 1] = a1;
    xsh[lane * 33 + f0 + 2] = a2;
    xsh[lane * 33 + f0 + 3] = a3;
    __syncthreads();

    if (tid < 32) {
        float ss = 0.f;
#pragma unroll
        for (int f = 0; f < 32; f++) { float v = xsh[tid * 33 + f]; ss += v * v; }
        nrm[tid] = fmaxf(sqrtf(ss), 1e-6f);
    }
    __syncthreads();

    float nm = nrm[lane];
    float o[4] = { a0 / nm, a1 / nm, a2 / nm, a3 / nm };
    *(float4*)(g_xn + (size_t)p * FF + f0) = *(float4*)o;

    __half* xr = g_xhi + (size_t)p * FF;
#pragma unroll
    for (int k = 0; k < 4; k++)
        xr[f0 + k] = __float2half_rn(o[k]);
}

// ---------------------------------------------------------------------------
// Kernel B: codebook L2 normalize + fragment-ordered fp16 store + inits.
// ---------------------------------------------------------------------------
__global__ void enorm_kernel(const float* __restrict__ emb)
{
    int tid  = threadIdx.x;
    int r    = blockIdx.x * 8 + (tid >> 5);
    int lane = tid & 31;
    float v = emb[(size_t)r * 32 + lane];
    float ss = v * v;
#pragma unroll
    for (int o = 16; o; o >>= 1) ss += __shfl_xor_sync(0xffffffffu, ss, o);
    float nm = fmaxf(sqrtf(ss), 1e-6f);
    float en = v / nm;
    g_en[(size_t)r * 32 + lane] = en;

    int k  = lane;
    int kt = k >> 4;
    int kr = k & 15;
    int fl = (r & 7) * 4 + ((kr & 7) >> 1);
    int el = (kr >> 3) * 2 + (kr & 1);
    g_ehi[(size_t)(r >> 3) * 256 + kt * 128 + fl * 4 + el] = __float2half_rn(en);

    if (tid < 8) g_hist[blockIdx.x * 8 + tid] = 0;
    if (blockIdx.x == 0 && tid == 0) g_nwork = 0;
}

// ---------------------------------------------------------------------------
// mma.sync m16n8k16 row.col fp16 -> f32
// ---------------------------------------------------------------------------
__device__ __forceinline__ void mma16816h(float* c, const uint32_t* a,
                                          uint32_t b0, uint32_t b1)
{
    asm volatile(
        "mma.sync.aligned.m16n8k16.row.col.f32.f16.f16.f32 "
        "{%0,%1,%2,%3}, {%4,%5,%6,%7}, {%8,%9}, {%0,%1,%2,%3};"
        : "+f"(c[0]), "+f"(c[1]), "+f"(c[2]), "+f"(c[3])
        : "r"(a[0]), "r"(a[1]), "r"(a[2]), "r"(a[3]), "r"(b0), "r"(b1));
}

__device__ __forceinline__ uint32_t smem_u32c(const void* p) {
    uint32_t a;
    asm("{ .reg .u64 t; cvta.to.shared.u64 t, %1; cvt.u32.u64 %0, t; }"
        : "=r"(a) : "l"(p));
    return a;
}

// exact fp32 dot (true cosine sim)
__device__ __forceinline__ float dot32(int p, int code)
{
    const float4* xr = (const float4*)(g_xn + (size_t)p * 32);
    const float4* er = (const float4*)(g_en + (size_t)code * 32);
    float s = 0.f;
#pragma unroll
    for (int q = 0; q < 8; q++) {
        float4 x = __ldg(xr + q), e = __ldg(er + q);
        s += x.x * e.x; s += x.y * e.y; s += x.z * e.z; s += x.w * e.w;
    }
    return s;
}

// order-preserving float -> uint32 (monotone for all finite floats)
__device__ __forceinline__ uint32_t f2ord(float f)
{
    uint32_t b = __float_as_uint(f);
    return (b & 0x80000000u) ? ~b : (b | 0x80000000u);
}
__device__ __forceinline__ unsigned long long packvi(float v, int idx)
{
    return ((unsigned long long)f2ord(v) << 32) | (uint32_t)(~(uint32_t)idx);
}

__device__ __forceinline__ void chunk_copy_async(uint32_t dbase, const char* src, int tid)
{
#pragma unroll
    for (int j = 0; j < 4; j++) {
        uint32_t d = dbase + (tid + 256 * j) * 16;
        asm volatile("cp.async.ca.shared.global [%0], [%1], 16;"
                     :: "r"(d), "l"(src + (tid + 256 * j) * 16) : "memory");
    }
    asm volatile("cp.async.commit_group;" ::: "memory");
}

// ---------------------------------------------------------------------------
// Kernel C: fp16 hi.hi approx sims, per-(pixel, 64-code granule) MAX only.
// 256 thr = 4 pixel-quarter warps x 2 code-half warps; chunk 256 codes.
// ---------------------------------------------------------------------------
__global__ void __launch_bounds__(256, 2) sims_max_kernel()
{
    extern __shared__ __half smc[];

    int tid  = threadIdx.x;
    int wid  = tid >> 5;
    int lane = tid & 31;
    int g    = lane >> 2;
    int kq   = lane & 3;
    int cw   = wid >> 2;
    int mw   = wid & 3;
    int px0  = blockIdx.x * 128;
    int cbase = blockIdx.y * CPS;

    // stage x-hi tile + extract A fragments (16 regs)
    for (int i = tid; i < 512; i += 256) {
        int r = i >> 2, q = i & 3;
        ((uint4*)(smc + r * XH_STR))[q] =
            ((const uint4*)(g_xhi + (size_t)(px0 + r) * 32))[q];
    }
    __syncthreads();
    uint32_t A[2][2][4];
#pragma unroll
    for (int kt = 0; kt < 2; kt++) {
        int k0 = kt * 16 + kq * 2;
#pragma unroll
        for (int mt = 0; mt < 2; mt++) {
            int r0 = mw * 32 + mt * 16 + g;
            A[kt][mt][0] = *(const uint32_t*)(smc + r0 * XH_STR + k0);
            A[kt][mt][1] = *(const uint32_t*)(smc + (r0 + 8) * XH_STR + k0);
            A[kt][mt][2] = *(const uint32_t*)(smc + r0 * XH_STR + k0 + 8);
            A[kt][mt][3] = *(const uint32_t*)(smc + (r0 + 8) * XH_STR + k0 + 8);
        }
    }
    __syncthreads();

    int pix[4];
#pragma unroll
    for (int s = 0; s < 4; s++) {
        int mt = s >> 1, h = s & 1;
        pix[s] = px0 + mw * 32 + mt * 16 + h * 8 + g;
    }

    uint32_t buf_base = smem_u32c(smc);
    chunk_copy_async(buf_base, (const char*)(g_ehi + (size_t)cbase * 32), tid);

    for (int ch = 0; ch < CPS; ch += CH2) {
        int cur = (ch >> 8) & 1;
        __syncthreads();
        if (ch + CH2 < CPS) {
            chunk_copy_async(buf_base + (cur ^ 1) * 16384,
                             (const char*)(g_ehi + (size_t)(cbase + ch + CH2) * 32), tid);
            asm volatile("cp.async.wait_group 1;" ::: "memory");
        } else {
            asm volatile("cp.async.wait_group 0;" ::: "memory");
        }
        __syncthreads();

        const char* ebuf = (const char*)smc + cur * 16384;

        float gm[2][4];   // [64-code granule within cw half][slot]
#pragma unroll
        for (int u = 0; u < 2; u++)
#pragma unroll
            for (int s = 0; s < 4; s++) gm[u][s] = -3.4e38f;

#pragma unroll
        for (int sub = 0; sub < 4; sub++) {
            const char* es = ebuf + (cw * 16 + sub * 4) * 512;

            float acc[4][2][4];
#pragma unroll
            for (int nt = 0; nt < 4; nt++)
#pragma unroll
                for (int mt = 0; mt < 2; mt++)
#pragma unroll
                    for (int c = 0; c < 4; c++) acc[nt][mt][c] = 0.f;

#pragma unroll
            for (int kt = 0; kt < 2; kt++) {
#pragma unroll
                for (int nt = 0; nt < 4; nt++) {
                    uint2 bb = *(const uint2*)(es + nt * 512 + kt * 256 + lane * 8);
                    mma16816h(acc[nt][0], A[kt][0], bb.x, bb.y);
                    mma16816h(acc[nt][1], A[kt][1], bb.x, bb.y);
                }
            }

            int u = sub >> 1;
#pragma unroll
            for (int mt = 0; mt < 2; mt++) {
#pragma unroll
                for (int h = 0; h < 2; h++) {
                    int s = mt * 2 + h;
                    float m01 = fmaxf(acc[0][mt][h * 2], acc[0][mt][h * 2 + 1]);
                    float m23 = fmaxf(acc[1][mt][h * 2], acc[1][mt][h * 2 + 1]);
                    float m45 = fmaxf(acc[2][mt][h * 2], acc[2][mt][h * 2 + 1]);
                    float m67 = fmaxf(acc[3][mt][h * 2], acc[3][mt][h * 2 + 1]);
                    gm[u][s] = fmaxf(gm[u][s],
                                     fmaxf(fmaxf(m01, m23), fmaxf(m45, m67)));
                }
            }
        }

        int cg = (cbase + ch) >> 8;
#pragma unroll
        for (int u = 0; u < 2; u++) {
#pragma unroll
            for (int s = 0; s < 4; s++) {
                float v = gm[u][s];
                v = fmaxf(v, __shfl_xor_sync(0xffffffffu, v, 1));
                v = fmaxf(v, __shfl_xor_sync(0xffffffffu, v, 2));
                if (kq == 0) {
                    int row = cg * 4 + cw * 2 + u;
                    g_cmax[(size_t)row * PIXELS + pix[s]] = v;
                }
            }
        }
    }
}

// ---------------------------------------------------------------------------
// Kernel FL: per-pixel threshold + flag granules within DELTA of max.
// High-MLP two-pass over g_cmax; also zeroes g_best (runs before scan).
// ---------------------------------------------------------------------------
__global__ void flag_kernel()
{
    int p = blockIdx.x * 256 + threadIdx.x;
    g_best[p] = 0ull;

    float M = -3.4e38f;
#pragma unroll 16
    for (int i = 0; i < NGRAN; i++)
        M = fmaxf(M, g_cmax[(size_t)i * PIXELS + p]);
    float th = M - DELTA;
#pragma unroll 16
    for (int i = 0; i < NGRAN; i++) {
        if (g_cmax[(size_t)i * PIXELS + p] >= th) {
            int w = atomicAdd(&g_nwork, 1);
            g_work[w] = (p << 8) | i;
        }
    }
}

// ---------------------------------------------------------------------------
// Kernel S: warp-per-granule exact fp32 rescore of flagged (pixel,granule).
// ---------------------------------------------------------------------------
__global__ void scan_kernel()
{
    int lane = threadIdx.x & 31;
    int gw   = (blockIdx.x * blockDim.x + threadIdx.x) >> 5;
    int nwarps = (gridDim.x * blockDim.x) >> 5;
    int n = g_nwork;

    for (int it = gw; it < n; it += nwarps) {
        int e = g_work[it];
        int p = e >> 8;
        int base = (e & 255) * 64;
        float bv = -3.4e38f;
        int   bi = 0x7fffffff;
#pragma unroll
        for (int j = 0; j < 2; j++) {
            int code = base + j * 32 + lane;
            float tv = dot32(p, code);
            if (tv > bv || (tv == bv && code < bi)) { bv = tv; bi = code; }
        }
#pragma unroll
        for (int o = 16; o; o >>= 1) {
            float ov = __shfl_xor_sync(0xffffffffu, bv, o);
            int   oi = __shfl_xor_sync(0xffffffffu, bi, o);
            if (ov > bv || (ov == bv && oi < bi)) { bv = ov; bi = oi; }
        }
        if (lane == 0)
            atomicMax(&g_best[p], packvi(bv, bi));
    }
}

// ---------------------------------------------------------------------------
// Kernel D: expansion GEMM + fused combine (closest/hist/loss on y==0).
// ---------------------------------------------------------------------------
__global__ void expand_kernel(const float* __restrict__ ew,
                              const float* __restrict__ eb,
                              float* __restrict__ out)
{
    __shared__ float Wsh[64 * 32];
    __shared__ float bsh[64];
    int tid = threadIdx.x;
    int d0  = blockIdx.y * 64;

    const float4* src = (const float4*)(ew + (size_t)d0 * 32);
    float4* dst = (float4*)Wsh;
    dst[tid]       = src[tid];
    dst[tid + 256] = src[tid + 256];
    if (tid < 64) bsh[tid] = eb[d0 + tid];
    __syncthreads();

    int p  = blockIdx.x * 256 + tid;
    int b  = p >> 10;
    int hw = p & 1023;
    unsigned long long bb = g_best[p];
    int idx = (int)(~(uint32_t)(bb & 0xffffffffu));

    float4 lat[8];
    const float4* lr = (const float4*)(g_en + (size_t)idx * 32);
#pragma unroll
    for (int q = 0; q < 8; q++) lat[q] = lr[q];

    if (blockIdx.y == 0) {
        out[CLOSEST_OFF + p] = (float)idx;
        atomicAdd(&g_hist[idx], 1);
        float s2 = 0.f;
        const float4* xr = (const float4*)(g_xn + (size_t)p * 32);
#pragma unroll
        for (int q = 0; q < 8; q++) {
            float4 x = xr[q];
            float d0_ = x.x - lat[q].x, d1 = x.y - lat[q].y;
            float d2 = x.z - lat[q].z, d3 = x.w - lat[q].w;
            s2 += d0_ * d0_; s2 += d1 * d1; s2 += d2 * d2; s2 += d3 * d3;
        }
        g_lossp[p] = s2;
    }

    float* outp = out + OUT_OFF + ((size_t)b * 512 + d0) * 1024 + hw;
#pragma unroll 2
    for (int dd = 0; dd < 64; dd++) {
        const float4* wr = (const float4*)(Wsh + dd * 32);
        float s = bsh[dd];
#pragma unroll
        for (int q = 0; q < 8; q++) {
            float4 w = wr[q];
            s += lat[q].x * w.x; s += lat[q].y * w.y;
            s += lat[q].z * w.z; s += lat[q].w * w.w;
        }
        outp[(size_t)dd * 1024] = s;
    }
}

// ---------------------------------------------------------------------------
// Kernel G: deterministic final reductions -> loss_q, perplexity
// ---------------------------------------------------------------------------
__global__ void finalize_kernel(float* __restrict__ out)
{
    __shared__ double sh[256];
    int tid = threadIdx.x;

    double ls = 0.0;
    for (int i = tid; i < PIXELS; i += 256) ls += (double)g_lossp[i];
    sh[tid] = ls;
    __syncthreads();
    for (int o = 128; o; o >>= 1) {
        if (tid < o) sh[tid] += sh[tid + o];
        __syncthreads();
    }
    double loss = sh[0] / (double)(PIXELS * 32);
    __syncthreads();

    double ps = 0.0;
    for (int i = tid; i < NN; i += 256) {
        float u = (float)g_hist[i] * (1.0f / 8192.0f);
        ps += (double)(-u * logf(u + 1e-6f));
    }
    sh[tid] = ps;
    __syncthreads();
    for (int o = 128; o; o >>= 1) {
        if (tid < o) sh[tid] += sh[tid + o];
        __syncthreads();
    }
    if (tid == 0) {
        out[LOSS_OFF] = (float)loss;
        out[PERP_OFF] = expf((float)sh[0]);
    }
}

// ---------------------------------------------------------------------------
extern "C" void kernel_launch(void* const* d_in, const int* in_sizes, int n_in,
                              void* d_out, int out_size)
{
    const float* enc = (const float*)d_in[0];  // [8,512,32,32]
    const float* emb = (const float*)d_in[1];  // [16384,32]
    const float* pw  = (const float*)d_in[2];  // [32,512]
    const float* pb  = (const float*)d_in[3];  // [32]
    const float* ew  = (const float*)d_in[4];  // [512,32]
    const float* eb  = (const float*)d_in[5];  // [512]
    float* out = (float*)d_out;

    (void)in_sizes; (void)n_in; (void)out_size;

    const int a_smem = (FF * DD + 32 * 33 + 32) * (int)sizeof(float); // 69888
    cudaFuncSetAttribute(proj_norm_kernel,
                         cudaFuncAttributeMaxDynamicSharedMemorySize, a_smem);

    const int c_smem = 32768;  // 2x16KB chunk buffers (x staging overlaps)
    cudaFuncSetAttribute(sims_max_kernel,
                         cudaFuncAttributeMaxDynamicSharedMemorySize, c_smem);

    proj_norm_kernel<<<256, 256, a_smem>>>(enc, pw, pb);
    enorm_kernel<<<2048, 256>>>(emb);
    sims_max_kernel<<<dim3(64, SPLITS), 256, c_smem>>>();
    flag_kernel<<<32, 256>>>();
    scan_kernel<<<296, 256>>>();
    expand_kernel<<<dim3(32, 8), 256>>>(ew, eb, out);
    finalize_kernel<<<1, 256>>>(out);
}

// round 16
// speedup vs baseline: 1.6679x; 1.2727x over previous
#include <cuda_runtime.h>
#include <cuda_fp16.h>
#include <cstdint>
#include <math.h>

// Problem constants
#define PIXELS 8192      // B*H*W = 8*32*32
#define DD 512
#define FF 32
#define NN 16384
#define HWSZ 1024
#define SPLITS 8
#define CPS (NN / SPLITS)   // 2048 codes per split (per blockIdx.y)
#define CH2 256             // codes per double-buffered chunk
#define XH_STR 40           // x-hi staging stride in halves (80B rows)
#define NGRAN 256           // 64-code granules over 16384 codes
#define DELTA 2.5e-3f       // >= 2 * fp16 hi.hi approx error bound

// Output layout (concatenated flattened outputs, float32):
#define OUT_OFF      0
#define CLOSEST_OFF  4194304
#define LOSS_OFF     4202496
#define PERP_OFF     4202497

// Scratch (no allocations allowed)
__device__ float g_xn[PIXELS * FF];       // normalized projected x, [p][32]
__device__ float g_en[NN * FF];           // normalized codebook, [n][32]
__device__ __half g_xhi[PIXELS * FF];     // fp16(xn), linear [p][32]
// g_ehi FRAGMENT-ordered: [code-group of 8][kt 0..1][lane 0..31][4 fp16]
__device__ __half g_ehi[NN * FF];
__device__ float g_cmax[PIXELS * NGRAN];  // approx max per (PIXEL, granule)
__device__ unsigned long long g_best[PIXELS]; // packed (ord(sim)<<32)|~idx
__device__ int   g_work[PIXELS * NGRAN / 8];  // flagged (pixel<<8)|granule
__device__ int   g_nwork;
__device__ int   g_hist[NN];
__device__ float g_lossp[PIXELS];

// ---------------------------------------------------------------------------
// Kernel A: 1x1 conv projection + channel L2 normalize + fp16 hi copy.
// ---------------------------------------------------------------------------
__global__ void proj_norm_kernel(const float* __restrict__ enc,
                                 const float* __restrict__ pw,
                                 const float* __restrict__ pb)
{
    extern __shared__ float sm[];
    float* Ws  = sm;                 // 32*512
    float* xsh = sm + FF * DD;       // 32*33 (padded)
    float* nrm = xsh + 32 * 33;      // 32

    int tid = threadIdx.x;

    const float4* W4 = (const float4*)pw;
    float4* Ws4 = (float4*)Ws;
#pragma unroll
    for (int i = 0; i < 16; i++) Ws4[tid + 256 * i] = W4[tid + 256 * i];
    __syncthreads();

    int lane = tid & 31;     // pixel within tile
    int fg   = tid >> 5;     // 0..7
    int f0   = fg * 4;
    int p    = blockIdx.x * 32 + lane;
    int b    = p >> 10;
    int hw   = p & 1023;

    const float* ep = enc + (size_t)b * DD * HWSZ + hw;
    const float4* w0 = (const float4*)(Ws + (size_t)(f0 + 0) * DD);
    const float4* w1 = (const float4*)(Ws + (size_t)(f0 + 1) * DD);
    const float4* w2 = (const float4*)(Ws + (size_t)(f0 + 2) * DD);
    const float4* w3 = (const float4*)(Ws + (size_t)(f0 + 3) * DD);

    float a0 = 0.f, a1 = 0.f, a2 = 0.f, a3 = 0.f;
#pragma unroll 4
    for (int q = 0; q < 128; q++) {
        float e0 = ep[(4 * q + 0) * HWSZ];
        float e1 = ep[(4 * q + 1) * HWSZ];
        float e2 = ep[(4 * q + 2) * HWSZ];
        float e3 = ep[(4 * q + 3) * HWSZ];
        float4 W0 = w0[q], W1 = w1[q], W2 = w2[q], W3 = w3[q];
        a0 += e0 * W0.x; a0 += e1 * W0.y; a0 += e2 * W0.z; a0 += e3 * W0.w;
        a1 += e0 * W1.x; a1 += e1 * W1.y; a1 += e2 * W1.z; a1 += e3 * W1.w;
        a2 += e0 * W2.x; a2 += e1 * W2.y; a2 += e2 * W2.z; a2 += e3 * W2.w;
        a3 += e0 * W3.x; a3 += e1 * W3.y; a3 += e2 * W3.z; a3 += e3 * W3.w;
    }
    a0 += pb[f0 + 0];
    a1 += pb[f0 + 1];
    a2 += pb[f0 + 2];
    a3 += pb[f0 + 3];

    xsh[lane * 33 + f0 + 0] = a0;
    xsh[lane * 33 + f0 + 1] = a1;
    xsh[lane * 33 + f0 + 2] = a2;
    xsh[lane * 33 + f0 + 3] = a3;
    __syncthreads();

    if (tid < 32) {
        float ss = 0.f;
#pragma unroll
        for (int f = 0; f < 32; f++) { float v = xsh[tid * 33 + f]; ss += v * v; }
        nrm[tid] = fmaxf(sqrtf(ss), 1e-6f);
    }
    __syncthreads();

    float nm = nrm[lane];
    float o[4] = { a0 / nm, a1 / nm, a2 / nm, a3 / nm };
    *(float4*)(g_xn + (size_t)p * FF + f0) = *(float4*)o;

    __half* xr = g_xhi + (size_t)p * FF;
#pragma unroll
    for (int k = 0; k < 4; k++)
        xr[f0 + k] = __float2half_rn(o[k]);
}

// ---------------------------------------------------------------------------
// Kernel B: codebook L2 normalize + fragment-ordered fp16 store + inits.
// ---------------------------------------------------------------------------
__global__ void enorm_kernel(const float* __restrict__ emb)
{
    int tid  = threadIdx.x;
    int r    = blockIdx.x * 8 + (tid >> 5);
    int lane = tid & 31;
    float v = emb[(size_t)r * 32 + lane];
    float ss = v * v;
#pragma unroll
    for (int o = 16; o; o >>= 1) ss += __shfl_xor_sync(0xffffffffu, ss, o);
    float nm = fmaxf(sqrtf(ss), 1e-6f);
    float en = v / nm;
    g_en[(size_t)r * 32 + lane] = en;

    int k  = lane;
    int kt = k >> 4;
    int kr = k & 15;
    int fl = (r & 7) * 4 + ((kr & 7) >> 1);
    int el = (kr >> 3) * 2 + (kr & 1);
    g_ehi[(size_t)(r >> 3) * 256 + kt * 128 + fl * 4 + el] = __float2half_rn(en);

    if (tid < 8) g_hist[blockIdx.x * 8 + tid] = 0;
    if (blockIdx.x == 0 && tid == 0) g_nwork = 0;
}

// ---------------------------------------------------------------------------
// mma.sync m16n8k16 row.col fp16 -> f32
// ---------------------------------------------------------------------------
__device__ __forceinline__ void mma16816h(float* c, const uint32_t* a,
                                          uint32_t b0, uint32_t b1)
{
    asm volatile(
        "mma.sync.aligned.m16n8k16.row.col.f32.f16.f16.f32 "
        "{%0,%1,%2,%3}, {%4,%5,%6,%7}, {%8,%9}, {%0,%1,%2,%3};"
        : "+f"(c[0]), "+f"(c[1]), "+f"(c[2]), "+f"(c[3])
        : "r"(a[0]), "r"(a[1]), "r"(a[2]), "r"(a[3]), "r"(b0), "r"(b1));
}

__device__ __forceinline__ uint32_t smem_u32c(const void* p) {
    uint32_t a;
    asm("{ .reg .u64 t; cvta.to.shared.u64 t, %1; cvt.u32.u64 %0, t; }"
        : "=r"(a) : "l"(p));
    return a;
}

// exact fp32 dot (true cosine sim)
__device__ __forceinline__ float dot32(int p, int code)
{
    const float4* xr = (const float4*)(g_xn + (size_t)p * 32);
    const float4* er = (const float4*)(g_en + (size_t)code * 32);
    float s = 0.f;
#pragma unroll
    for (int q = 0; q < 8; q++) {
        float4 x = __ldg(xr + q), e = __ldg(er + q);
        s += x.x * e.x; s += x.y * e.y; s += x.z * e.z; s += x.w * e.w;
    }
    return s;
}

// order-preserving float -> uint32 (monotone for all finite floats)
__device__ __forceinline__ uint32_t f2ord(float f)
{
    uint32_t b = __float_as_uint(f);
    return (b & 0x80000000u) ? ~b : (b | 0x80000000u);
}
__device__ __forceinline__ unsigned long long packvi(float v, int idx)
{
    return ((unsigned long long)f2ord(v) << 32) | (uint32_t)(~(uint32_t)idx);
}

__device__ __forceinline__ void chunk_copy_async(uint32_t dbase, const char* src, int tid)
{
#pragma unroll
    for (int j = 0; j < 4; j++) {
        uint32_t d = dbase + (tid + 256 * j) * 16;
        asm volatile("cp.async.ca.shared.global [%0], [%1], 16;"
                     :: "r"(d), "l"(src + (tid + 256 * j) * 16) : "memory");
    }
    asm volatile("cp.async.commit_group;" ::: "memory");
}

// ---------------------------------------------------------------------------
// Kernel C: fp16 hi.hi approx sims, per-(pixel, 64-code granule) MAX only.
// g_cmax is stored PIXEL-major for the flag kernel's coalesced reads.
// ---------------------------------------------------------------------------
__global__ void __launch_bounds__(256, 2) sims_max_kernel()
{
    extern __shared__ __half smc[];

    int tid  = threadIdx.x;
    int wid  = tid >> 5;
    int lane = tid & 31;
    int g    = lane >> 2;
    int kq   = lane & 3;
    int cw   = wid >> 2;
    int mw   = wid & 3;
    int px0  = blockIdx.x * 128;
    int cbase = blockIdx.y * CPS;

    // stage x-hi tile + extract A fragments (16 regs)
    for (int i = tid; i < 512; i += 256) {
        int r = i >> 2, q = i & 3;
        ((uint4*)(smc + r * XH_STR))[q] =
            ((const uint4*)(g_xhi + (size_t)(px0 + r) * 32))[q];
    }
    __syncthreads();
    uint32_t A[2][2][4];
#pragma unroll
    for (int kt = 0; kt < 2; kt++) {
        int k0 = kt * 16 + kq * 2;
#pragma unroll
        for (int mt = 0; mt < 2; mt++) {
            int r0 = mw * 32 + mt * 16 + g;
            A[kt][mt][0] = *(const uint32_t*)(smc + r0 * XH_STR + k0);
            A[kt][mt][1] = *(const uint32_t*)(smc + (r0 + 8) * XH_STR + k0);
            A[kt][mt][2] = *(const uint32_t*)(smc + r0 * XH_STR + k0 + 8);
            A[kt][mt][3] = *(const uint32_t*)(smc + (r0 + 8) * XH_STR + k0 + 8);
        }
    }
    __syncthreads();

    int pix[4];
#pragma unroll
    for (int s = 0; s < 4; s++) {
        int mt = s >> 1, h = s & 1;
        pix[s] = px0 + mw * 32 + mt * 16 + h * 8 + g;
    }

    uint32_t buf_base = smem_u32c(smc);
    chunk_copy_async(buf_base, (const char*)(g_ehi + (size_t)cbase * 32), tid);

    for (int ch = 0; ch < CPS; ch += CH2) {
        int cur = (ch >> 8) & 1;
        __syncthreads();
        if (ch + CH2 < CPS) {
            chunk_copy_async(buf_base + (cur ^ 1) * 16384,
                             (const char*)(g_ehi + (size_t)(cbase + ch + CH2) * 32), tid);
            asm volatile("cp.async.wait_group 1;" ::: "memory");
        } else {
            asm volatile("cp.async.wait_group 0;" ::: "memory");
        }
        __syncthreads();

        const char* ebuf = (const char*)smc + cur * 16384;

        float gm[2][4];   // [64-code granule within cw half][slot]
#pragma unroll
        for (int u = 0; u < 2; u++)
#pragma unroll
            for (int s = 0; s < 4; s++) gm[u][s] = -3.4e38f;

#pragma unroll
        for (int sub = 0; sub < 4; sub++) {
            const char* es = ebuf + (cw * 16 + sub * 4) * 512;

            float acc[4][2][4];
#pragma unroll
            for (int nt = 0; nt < 4; nt++)
#pragma unroll
                for (int mt = 0; mt < 2; mt++)
#pragma unroll
                    for (int c = 0; c < 4; c++) acc[nt][mt][c] = 0.f;

#pragma unroll
            for (int kt = 0; kt < 2; kt++) {
#pragma unroll
                for (int nt = 0; nt < 4; nt++) {
                    uint2 bb = *(const uint2*)(es + nt * 512 + kt * 256 + lane * 8);
                    mma16816h(acc[nt][0], A[kt][0], bb.x, bb.y);
                    mma16816h(acc[nt][1], A[kt][1], bb.x, bb.y);
                }
            }

            int u = sub >> 1;
#pragma unroll
            for (int mt = 0; mt < 2; mt++) {
#pragma unroll
                for (int h = 0; h < 2; h++) {
                    int s = mt * 2 + h;
                    float m01 = fmaxf(acc[0][mt][h * 2], acc[0][mt][h * 2 + 1]);
                    float m23 = fmaxf(acc[1][mt][h * 2], acc[1][mt][h * 2 + 1]);
                    float m45 = fmaxf(acc[2][mt][h * 2], acc[2][mt][h * 2 + 1]);
                    float m67 = fmaxf(acc[3][mt][h * 2], acc[3][mt][h * 2 + 1]);
                    gm[u][s] = fmaxf(gm[u][s],
                                     fmaxf(fmaxf(m01, m23), fmaxf(m45, m67)));
                }
            }
        }

        int cg = (cbase + ch) >> 8;
#pragma unroll
        for (int u = 0; u < 2; u++) {
#pragma unroll
            for (int s = 0; s < 4; s++) {
                float v = gm[u][s];
                v = fmaxf(v, __shfl_xor_sync(0xffffffffu, v, 1));
                v = fmaxf(v, __shfl_xor_sync(0xffffffffu, v, 2));
                if (kq == 0) {
                    int row = cg * 4 + cw * 2 + u;   // 64-code granule id
                    g_cmax[(size_t)pix[s] * NGRAN + row] = v;
                }
            }
        }
    }
}

// ---------------------------------------------------------------------------
// Kernel FL: warp-per-pixel flag. Coalesced 1KB row per pixel, values kept
// in registers for the flag pass; also zeroes g_best.
// grid 256 x 256 thr: 2048 warps, 4 pixels each.
// ---------------------------------------------------------------------------
__global__ void flag_kernel()
{
    int lane = threadIdx.x & 31;
    int warp = (blockIdx.x * blockDim.x + threadIdx.x) >> 5;

#pragma unroll
    for (int pi = 0; pi < 4; pi++) {
        int p = warp * 4 + pi;
        if (lane == 0) g_best[p] = 0ull;

        const float* row = g_cmax + (size_t)p * NGRAN;
        float v[8];
        float m = -3.4e38f;
#pragma unroll
        for (int j = 0; j < 8; j++) {
            v[j] = row[j * 32 + lane];
            m = fmaxf(m, v[j]);
        }
#pragma unroll
        for (int o = 16; o; o >>= 1)
            m = fmaxf(m, __shfl_xor_sync(0xffffffffu, m, o));
        float th = m - DELTA;
#pragma unroll
        for (int j = 0; j < 8; j++) {
            if (v[j] >= th) {
                int w = atomicAdd(&g_nwork, 1);
                g_work[w] = (p << 8) | (j * 32 + lane);
            }
        }
    }
}

// ---------------------------------------------------------------------------
// Kernel S: warp-per-granule exact fp32 rescore of flagged (pixel,granule).
// ---------------------------------------------------------------------------
__global__ void scan_kernel()
{
    int lane = threadIdx.x & 31;
    int gw   = (blockIdx.x * blockDim.x + threadIdx.x) >> 5;
    int nwarps = (gridDim.x * blockDim.x) >> 5;
    int n = g_nwork;

    for (int it = gw; it < n; it += nwarps) {
        int e = g_work[it];
        int p = e >> 8;
        int base = (e & 255) * 64;
        float bv = -3.4e38f;
        int   bi = 0x7fffffff;
#pragma unroll
        for (int j = 0; j < 2; j++) {
            int code = base + j * 32 + lane;
            float tv = dot32(p, code);
            if (tv > bv || (tv == bv && code < bi)) { bv = tv; bi = code; }
        }
#pragma unroll
        for (int o = 16; o; o >>= 1) {
            float ov = __shfl_xor_sync(0xffffffffu, bv, o);
            int   oi = __shfl_xor_sync(0xffffffffu, bi, o);
            if (ov > bv || (ov == bv && oi < bi)) { bv = ov; bi = oi; }
        }
        if (lane == 0)
            atomicMax(&g_best[p], packvi(bv, bi));
    }
}

// ---------------------------------------------------------------------------
// Kernel D: expansion GEMM + fused combine (closest/hist/loss on y==0).
// ---------------------------------------------------------------------------
__global__ void expand_kernel(const float* __restrict__ ew,
                              const float* __restrict__ eb,
                              float* __restrict__ out)
{
    __shared__ float Wsh[64 * 32];
    __shared__ float bsh[64];
    int tid = threadIdx.x;
    int d0  = blockIdx.y * 64;

    const float4* src = (const float4*)(ew + (size_t)d0 * 32);
    float4* dst = (float4*)Wsh;
    dst[tid]       = src[tid];
    dst[tid + 256] = src[tid + 256];
    if (tid < 64) bsh[tid] = eb[d0 + tid];
    __syncthreads();

    int p  = blockIdx.x * 256 + tid;
    int b  = p >> 10;
    int hw = p & 1023;
    unsigned long long bb = g_best[p];
    int idx = (int)(~(uint32_t)(bb & 0xffffffffu));

    float4 lat[8];
    const float4* lr = (const float4*)(g_en + (size_t)idx * 32);
#pragma unroll
    for (int q = 0; q < 8; q++) lat[q] = lr[q];

    if (blockIdx.y == 0) {
        out[CLOSEST_OFF + p] = (float)idx;
        atomicAdd(&g_hist[idx], 1);
        float s2 = 0.f;
        const float4* xr = (const float4*)(g_xn + (size_t)p * 32);
#pragma unroll
        for (int q = 0; q < 8; q++) {
            float4 x = xr[q];
            float d0_ = x.x - lat[q].x, d1 = x.y - lat[q].y;
            float d2 = x.z - lat[q].z, d3 = x.w - lat[q].w;
            s2 += d0_ * d0_; s2 += d1 * d1; s2 += d2 * d2; s2 += d3 * d3;
        }
        g_lossp[p] = s2;
    }

    float* outp = out + OUT_OFF + ((size_t)b * 512 + d0) * 1024 + hw;
#pragma unroll 2
    for (int dd = 0; dd < 64; dd++) {
        const float4* wr = (const float4*)(Wsh + dd * 32);
        float s = bsh[dd];
#pragma unroll
        for (int q = 0; q < 8; q++) {
            float4 w = wr[q];
            s += lat[q].x * w.x; s += lat[q].y * w.y;
            s += lat[q].z * w.z; s += lat[q].w * w.w;
        }
        outp[(size_t)dd * 1024] = s;
    }
}

// ---------------------------------------------------------------------------
// Kernel G: deterministic final reductions -> loss_q, perplexity
// ---------------------------------------------------------------------------
__global__ void finalize_kernel(float* __restrict__ out)
{
    __shared__ double sh[256];
    int tid = threadIdx.x;

    double ls = 0.0;
    for (int i = tid; i < PIXELS; i += 256) ls += (double)g_lossp[i];
    sh[tid] = ls;
    __syncthreads();
    for (int o = 128; o; o >>= 1) {
        if (tid < o) sh[tid] += sh[tid + o];
        __syncthreads();
    }
    double loss = sh[0] / (double)(PIXELS * 32);
    __syncthreads();

    double ps = 0.0;
    for (int i = tid; i < NN; i += 256) {
        float u = (float)g_hist[i] * (1.0f / 8192.0f);
        ps += (double)(-u * logf(u + 1e-6f));
    }
    sh[tid] = ps;
    __syncthreads();
    for (int o = 128; o; o >>= 1) {
        if (tid < o) sh[tid] += sh[tid + o];
        __syncthreads();
    }
    if (tid == 0) {
        out[LOSS_OFF] = (float)loss;
        out[PERP_OFF] = expf((float)sh[0]);
    }
}

// ---------------------------------------------------------------------------
extern "C" void kernel_launch(void* const* d_in, const int* in_sizes, int n_in,
                              void* d_out, int out_size)
{
    const float* enc = (const float*)d_in[0];  // [8,512,32,32]
    const float* emb = (const float*)d_in[1];  // [16384,32]
    const float* pw  = (const float*)d_in[2];  // [32,512]
    const float* pb  = (const float*)d_in[3];  // [32]
    const float* ew  = (const float*)d_in[4];  // [512,32]
    const float* eb  = (const float*)d_in[5];  // [512]
    float* out = (float*)d_out;

    (void)in_sizes; (void)n_in; (void)out_size;

    const int a_smem = (FF * DD + 32 * 33 + 32) * (int)sizeof(float); // 69888
    cudaFuncSetAttribute(proj_norm_kernel,
                         cudaFuncAttributeMaxDynamicSharedMemorySize, a_smem);

    const int c_smem = 32768;  // 2x16KB chunk buffers (x staging overlaps)
    cudaFuncSetAttribute(sims_max_kernel,
                         cudaFuncAttributeMaxDynamicSharedMemorySize, c_smem);

    proj_norm_kernel<<<256, 256, a_smem>>>(enc, pw, pb);
    enorm_kernel<<<2048, 256>>>(emb);
    sims_max_kernel<<<dim3(64, SPLITS), 256, c_smem>>>();
    flag_kernel<<<256, 256>>>();
    scan_kernel<<<296, 256>>>();
    expand_kernel<<<dim3(32, 8), 256>>>(ew, eb, out);
    finalize_kernel<<<1, 256>>>(out);
}

// round 17
// speedup vs baseline: 1.6935x; 1.0154x over previous
#include <cuda_runtime.h>
#include <cuda_fp16.h>
#include <cstdint>
#include <math.h>

// Problem constants
#define PIXELS 8192      // B*H*W = 8*32*32
#define DD 512
#define FF 32
#define NN 16384
#define HWSZ 1024
#define SPLITS 8
#define CPS (NN / SPLITS)   // 2048 codes per split (per blockIdx.y)
#define CH2 256             // codes per double-buffered chunk
#define XH_STR 40           // x-hi staging stride in halves (80B rows)
#define NGRAN 256           // 64-code granules over 16384 codes
#define DELTA 2.5e-3f       // >= 2 * fp16 hi.hi approx error bound

// Output layout (concatenated flattened outputs, float32):
#define OUT_OFF      0
#define CLOSEST_OFF  4194304
#define LOSS_OFF     4202496
#define PERP_OFF     4202497

// Scratch (no allocations allowed)
__device__ float g_xn[PIXELS * FF];       // normalized projected x, [p][32]
__device__ float g_en[NN * FF];           // normalized codebook, [n][32]
__device__ __half g_xhi[PIXELS * FF];     // fp16(xn), linear [p][32]
// g_ehi FRAGMENT-ordered: [code-group of 8][kt 0..1][lane 0..31][4 fp16]
__device__ __half g_ehi[NN * FF];
__device__ float g_cmax[PIXELS * NGRAN];  // approx max per (PIXEL, granule)
__device__ unsigned long long g_best[PIXELS]; // packed (ord(sim)<<32)|~idx
__device__ int   g_work[PIXELS * NGRAN / 8];  // flagged (pixel<<8)|granule
__device__ int   g_nwork;
__device__ int   g_hist[NN];
__device__ float g_lossp[PIXELS];

// ---------------------------------------------------------------------------
// Kernel P (fused A+B): blocks [0,256) = 1x1 conv projection + L2 norm +
// fp16 hi copy; blocks [256,768) = codebook L2 normalize + fragment store.
// ---------------------------------------------------------------------------
__global__ void prep_kernel(const float* __restrict__ enc,
                            const float* __restrict__ pw,
                            const float* __restrict__ pb,
                            const float* __restrict__ emb)
{
    int tid = threadIdx.x;

    if (blockIdx.x >= 256) {
        // ---- enorm part: 512 blocks x 32 codebook rows ----
        int bid  = blockIdx.x - 256;
        int lane = tid & 31;
        int w    = tid >> 5;
#pragma unroll
        for (int i = 0; i < 4; i++) {
            int r = bid * 32 + w * 4 + i;
            float v = emb[(size_t)r * 32 + lane];
            float ss = v * v;
#pragma unroll
            for (int o = 16; o; o >>= 1) ss += __shfl_xor_sync(0xffffffffu, ss, o);
            float nm = fmaxf(sqrtf(ss), 1e-6f);
            float en = v / nm;
            g_en[(size_t)r * 32 + lane] = en;

            int k  = lane;
            int kt = k >> 4;
            int kr = k & 15;
            int fl = (r & 7) * 4 + ((kr & 7) >> 1);
            int el = (kr >> 3) * 2 + (kr & 1);
            g_ehi[(size_t)(r >> 3) * 256 + kt * 128 + fl * 4 + el] =
                __float2half_rn(en);
        }
        if (tid < 32) g_hist[bid * 32 + tid] = 0;
        if (bid == 0 && tid == 0) g_nwork = 0;
        return;
    }

    // ---- proj part ----
    extern __shared__ float sm[];
    float* Ws  = sm;                 // 32*512
    float* xsh = sm + FF * DD;       // 32*33 (padded)
    float* nrm = xsh + 32 * 33;      // 32

    const float4* W4 = (const float4*)pw;
    float4* Ws4 = (float4*)Ws;
#pragma unroll
    for (int i = 0; i < 16; i++) Ws4[tid + 256 * i] = W4[tid + 256 * i];
    __syncthreads();

    int lane = tid & 31;     // pixel within tile
    int fg   = tid >> 5;     // 0..7
    int f0   = fg * 4;
    int p    = blockIdx.x * 32 + lane;
    int b    = p >> 10;
    int hw   = p & 1023;

    const float* ep = enc + (size_t)b * DD * HWSZ + hw;
    const float4* w0 = (const float4*)(Ws + (size_t)(f0 + 0) * DD);
    const float4* w1 = (const float4*)(Ws + (size_t)(f0 + 1) * DD);
    const float4* w2 = (const float4*)(Ws + (size_t)(f0 + 2) * DD);
    const float4* w3 = (const float4*)(Ws + (size_t)(f0 + 3) * DD);

    float a0 = 0.f, a1 = 0.f, a2 = 0.f, a3 = 0.f;
#pragma unroll 4
    for (int q = 0; q < 128; q++) {
        float e0 = ep[(4 * q + 0) * HWSZ];
        float e1 = ep[(4 * q + 1) * HWSZ];
        float e2 = ep[(4 * q + 2) * HWSZ];
        float e3 = ep[(4 * q + 3) * HWSZ];
        float4 W0 = w0[q], W1 = w1[q], W2 = w2[q], W3 = w3[q];
        a0 += e0 * W0.x; a0 += e1 * W0.y; a0 += e2 * W0.z; a0 += e3 * W0.w;
        a1 += e0 * W1.x; a1 += e1 * W1.y; a1 += e2 * W1.z; a1 += e3 * W1.w;
        a2 += e0 * W2.x; a2 += e1 * W2.y; a2 += e2 * W2.z; a2 += e3 * W2.w;
        a3 += e0 * W3.x; a3 += e1 * W3.y; a3 += e2 * W3.z; a3 += e3 * W3.w;
    }
    a0 += pb[f0 + 0];
    a1 += pb[f0 + 1];
    a2 += pb[f0 + 2];
    a3 += pb[f0 + 3];

    xsh[lane * 33 + f0 + 0] = a0;
    xsh[lane * 33 + f0 + 1] = a1;
    xsh[lane * 33 + f0 + 2] = a2;
    xsh[lane * 33 + f0 + 3] = a3;
    __syncthreads();

    if (tid < 32) {
        float ss = 0.f;
#pragma unroll
        for (int f = 0; f < 32; f++) { float v = xsh[tid * 33 + f]; ss += v * v; }
        nrm[tid] = fmaxf(sqrtf(ss), 1e-6f);
    }
    __syncthreads();

    float nm = nrm[lane];
    float o[4] = { a0 / nm, a1 / nm, a2 / nm, a3 / nm };
    *(float4*)(g_xn + (size_t)p * FF + f0) = *(float4*)o;

    __half* xr = g_xhi + (size_t)p * FF;
#pragma unroll
    for (int k = 0; k < 4; k++)
        xr[f0 + k] = __float2half_rn(o[k]);
}

// ---------------------------------------------------------------------------
// mma.sync m16n8k16 row.col fp16 -> f32
// ---------------------------------------------------------------------------
__device__ __forceinline__ void mma16816h(float* c, const uint32_t* a,
                                          uint32_t b0, uint32_t b1)
{
    asm volatile(
        "mma.sync.aligned.m16n8k16.row.col.f32.f16.f16.f32 "
        "{%0,%1,%2,%3}, {%4,%5,%6,%7}, {%8,%9}, {%0,%1,%2,%3};"
        : "+f"(c[0]), "+f"(c[1]), "+f"(c[2]), "+f"(c[3])
        : "r"(a[0]), "r"(a[1]), "r"(a[2]), "r"(a[3]), "r"(b0), "r"(b1));
}

__device__ __forceinline__ uint32_t smem_u32c(const void* p) {
    uint32_t a;
    asm("{ .reg .u64 t; cvta.to.shared.u64 t, %1; cvt.u32.u64 %0, t; }"
        : "=r"(a) : "l"(p));
    return a;
}

// exact fp32 dot (true cosine sim)
__device__ __forceinline__ float dot32(int p, int code)
{
    const float4* xr = (const float4*)(g_xn + (size_t)p * 32);
    const float4* er = (const float4*)(g_en + (size_t)code * 32);
    float s = 0.f;
#pragma unroll
    for (int q = 0; q < 8; q++) {
        float4 x = __ldg(xr + q), e = __ldg(er + q);
        s += x.x * e.x; s += x.y * e.y; s += x.z * e.z; s += x.w * e.w;
    }
    return s;
}

// order-preserving float -> uint32 (monotone for all finite floats)
__device__ __forceinline__ uint32_t f2ord(float f)
{
    uint32_t b = __float_as_uint(f);
    return (b & 0x80000000u) ? ~b : (b | 0x80000000u);
}
__device__ __forceinline__ unsigned long long packvi(float v, int idx)
{
    return ((unsigned long long)f2ord(v) << 32) | (uint32_t)(~(uint32_t)idx);
}

__device__ __forceinline__ void chunk_copy_async(uint32_t dbase, const char* src, int tid)
{
#pragma unroll
    for (int j = 0; j < 4; j++) {
        uint32_t d = dbase + (tid + 256 * j) * 16;
        asm volatile("cp.async.ca.shared.global [%0], [%1], 16;"
                     :: "r"(d), "l"(src + (tid + 256 * j) * 16) : "memory");
    }
    asm volatile("cp.async.commit_group;" ::: "memory");
}

// ---------------------------------------------------------------------------
// Kernel C: fp16 hi.hi approx sims, per-(pixel, 64-code granule) MAX only.
// g_cmax is stored PIXEL-major for the flag kernel's coalesced reads.
// ---------------------------------------------------------------------------
__global__ void __launch_bounds__(256, 2) sims_max_kernel()
{
    extern __shared__ __half smc[];

    int tid  = threadIdx.x;
    int wid  = tid >> 5;
    int lane = tid & 31;
    int g    = lane >> 2;
    int kq   = lane & 3;
    int cw   = wid >> 2;
    int mw   = wid & 3;
    int px0  = blockIdx.x * 128;
    int cbase = blockIdx.y * CPS;

    // stage x-hi tile + extract A fragments (16 regs)
    for (int i = tid; i < 512; i += 256) {
        int r = i >> 2, q = i & 3;
        ((uint4*)(smc + r * XH_STR))[q] =
            ((const uint4*)(g_xhi + (size_t)(px0 + r) * 32))[q];
    }
    __syncthreads();
    uint32_t A[2][2][4];
#pragma unroll
    for (int kt = 0; kt < 2; kt++) {
        int k0 = kt * 16 + kq * 2;
#pragma unroll
        for (int mt = 0; mt < 2; mt++) {
            int r0 = mw * 32 + mt * 16 + g;
            A[kt][mt][0] = *(const uint32_t*)(smc + r0 * XH_STR + k0);
            A[kt][mt][1] = *(const uint32_t*)(smc + (r0 + 8) * XH_STR + k0);
            A[kt][mt][2] = *(const uint32_t*)(smc + r0 * XH_STR + k0 + 8);
            A[kt][mt][3] = *(const uint32_t*)(smc + (r0 + 8) * XH_STR + k0 + 8);
        }
    }
    __syncthreads();

    int pix[4];
#pragma unroll
    for (int s = 0; s < 4; s++) {
        int mt = s >> 1, h = s & 1;
        pix[s] = px0 + mw * 32 + mt * 16 + h * 8 + g;
    }

    uint32_t buf_base = smem_u32c(smc);
    chunk_copy_async(buf_base, (const char*)(g_ehi + (size_t)cbase * 32), tid);

    for (int ch = 0; ch < CPS; ch += CH2) {
        int cur = (ch >> 8) & 1;
        __syncthreads();
        if (ch + CH2 < CPS) {
            chunk_copy_async(buf_base + (cur ^ 1) * 16384,
                             (const char*)(g_ehi + (size_t)(cbase + ch + CH2) * 32), tid);
            asm volatile("cp.async.wait_group 1;" ::: "memory");
        } else {
            asm volatile("cp.async.wait_group 0;" ::: "memory");
        }
        __syncthreads();

        const char* ebuf = (const char*)smc + cur * 16384;

        float gm[2][4];   // [64-code granule within cw half][slot]
#pragma unroll
        for (int u = 0; u < 2; u++)
#pragma unroll
            for (int s = 0; s < 4; s++) gm[u][s] = -3.4e38f;

#pragma unroll
        for (int sub = 0; sub < 4; sub++) {
            const char* es = ebuf + (cw * 16 + sub * 4) * 512;

            float acc[4][2][4];
#pragma unroll
            for (int nt = 0; nt < 4; nt++)
#pragma unroll
                for (int mt = 0; mt < 2; mt++)
#pragma unroll
                    for (int c = 0; c < 4; c++) acc[nt][mt][c] = 0.f;

#pragma unroll
            for (int kt = 0; kt < 2; kt++) {
#pragma unroll
                for (int nt = 0; nt < 4; nt++) {
                    uint2 bb = *(const uint2*)(es + nt * 512 + kt * 256 + lane * 8);
                    mma16816h(acc[nt][0], A[kt][0], bb.x, bb.y);
                    mma16816h(acc[nt][1], A[kt][1], bb.x, bb.y);
                }
            }

            int u = sub >> 1;
#pragma unroll
            for (int mt = 0; mt < 2; mt++) {
#pragma unroll
                for (int h = 0; h < 2; h++) {
                    int s = mt * 2 + h;
                    float m01 = fmaxf(acc[0][mt][h * 2], acc[0][mt][h * 2 + 1]);
                    float m23 = fmaxf(acc[1][mt][h * 2], acc[1][mt][h * 2 + 1]);
                    float m45 = fmaxf(acc[2][mt][h * 2], acc[2][mt][h * 2 + 1]);
                    float m67 = fmaxf(acc[3][mt][h * 2], acc[3][mt][h * 2 + 1]);
                    gm[u][s] = fmaxf(gm[u][s],
                                     fmaxf(fmaxf(m01, m23), fmaxf(m45, m67)));
                }
            }
        }

        int cg = (cbase + ch) >> 8;
#pragma unroll
        for (int u = 0; u < 2; u++) {
#pragma unroll
            for (int s = 0; s < 4; s++) {
                float v = gm[u][s];
                v = fmaxf(v, __shfl_xor_sync(0xffffffffu, v, 1));
                v = fmaxf(v, __shfl_xor_sync(0xffffffffu, v, 2));
                if (kq == 0) {
                    int row = cg * 4 + cw * 2 + u;   // 64-code granule id
                    g_cmax[(size_t)pix[s] * NGRAN + row] = v;
                }
            }
        }
    }
}

// ---------------------------------------------------------------------------
// Kernel FL: warp-per-pixel flag (2 px/warp). Coalesced 1KB row per pixel,
// values kept in registers for the flag pass; also zeroes g_best.
// grid 512 x 256 thr: 4096 warps, 2 pixels each.
// ---------------------------------------------------------------------------
__global__ void flag_kernel()
{
    int lane = threadIdx.x & 31;
    int warp = (blockIdx.x * blockDim.x + threadIdx.x) >> 5;

#pragma unroll
    for (int pi = 0; pi < 2; pi++) {
        int p = warp * 2 + pi;
        if (lane == 0) g_best[p] = 0ull;

        const float* row = g_cmax + (size_t)p * NGRAN;
        float v[8];
        float m = -3.4e38f;
#pragma unroll
        for (int j = 0; j < 8; j++) {
            v[j] = row[j * 32 + lane];
            m = fmaxf(m, v[j]);
        }
#pragma unroll
        for (int o = 16; o; o >>= 1)
            m = fmaxf(m, __shfl_xor_sync(0xffffffffu, m, o));
        float th = m - DELTA;
#pragma unroll
        for (int j = 0; j < 8; j++) {
            if (v[j] >= th) {
                int w = atomicAdd(&g_nwork, 1);
                g_work[w] = (p << 8) | (j * 32 + lane);
            }
        }
    }
}

// ---------------------------------------------------------------------------
// Kernel S: warp-per-granule exact fp32 rescore of flagged (pixel,granule).
// ---------------------------------------------------------------------------
__global__ void scan_kernel()
{
    int lane = threadIdx.x & 31;
    int gw   = (blockIdx.x * blockDim.x + threadIdx.x) >> 5;
    int nwarps = (gridDim.x * blockDim.x) >> 5;
    int n = g_nwork;

    for (int it = gw; it < n; it += nwarps) {
        int e = g_work[it];
        int p = e >> 8;
        int base = (e & 255) * 64;
        float bv = -3.4e38f;
        int   bi = 0x7fffffff;
#pragma unroll
        for (int j = 0; j < 2; j++) {
            int code = base + j * 32 + lane;
            float tv = dot32(p, code);
            if (tv > bv || (tv == bv && code < bi)) { bv = tv; bi = code; }
        }
#pragma unroll
        for (int o = 16; o; o >>= 1) {
            float ov = __shfl_xor_sync(0xffffffffu, bv, o);
            int   oi = __shfl_xor_sync(0xffffffffu, bi, o);
            if (ov > bv || (ov == bv && oi < bi)) { bv = ov; bi = oi; }
        }
        if (lane == 0)
            atomicMax(&g_best[p], packvi(bv, bi));
    }
}

// ---------------------------------------------------------------------------
// Kernel D: expansion GEMM + fused combine (closest/hist/loss on y==0).
// ---------------------------------------------------------------------------
__global__ void expand_kernel(const float* __restrict__ ew,
                              const float* __restrict__ eb,
                              float* __restrict__ out)
{
    __shared__ float Wsh[64 * 32];
    __shared__ float bsh[64];
    int tid = threadIdx.x;
    int d0  = blockIdx.y * 64;

    const float4* src = (const float4*)(ew + (size_t)d0 * 32);
    float4* dst = (float4*)Wsh;
    dst[tid]       = src[tid];
    dst[tid + 256] = src[tid + 256];
    if (tid < 64) bsh[tid] = eb[d0 + tid];
    __syncthreads();

    int p  = blockIdx.x * 256 + tid;
    int b  = p >> 10;
    int hw = p & 1023;
    unsigned long long bb = g_best[p];
    int idx = (int)(~(uint32_t)(bb & 0xffffffffu));

    float4 lat[8];
    const float4* lr = (const float4*)(g_en + (size_t)idx * 32);
#pragma unroll
    for (int q = 0; q < 8; q++) lat[q] = lr[q];

    if (blockIdx.y == 0) {
        out[CLOSEST_OFF + p] = (float)idx;
        atomicAdd(&g_hist[idx], 1);
        float s2 = 0.f;
        const float4* xr = (const float4*)(g_xn + (size_t)p * 32);
#pragma unroll
        for (int q = 0; q < 8; q++) {
            float4 x = xr[q];
            float d0_ = x.x - lat[q].x, d1 = x.y - lat[q].y;
            float d2 = x.z - lat[q].z, d3 = x.w - lat[q].w;
            s2 += d0_ * d0_; s2 += d1 * d1; s2 += d2 * d2; s2 += d3 * d3;
        }
        g_lossp[p] = s2;
    }

    float* outp = out + OUT_OFF + ((size_t)b * 512 + d0) * 1024 + hw;
#pragma unroll 2
    for (int dd = 0; dd < 64; dd++) {
        const float4* wr = (const float4*)(Wsh + dd * 32);
        float s = bsh[dd];
#pragma unroll
        for (int q = 0; q < 8; q++) {
            float4 w = wr[q];
            s += lat[q].x * w.x; s += lat[q].y * w.y;
            s += lat[q].z * w.z; s += lat[q].w * w.w;
        }
        outp[(size_t)dd * 1024] = s;
    }
}

// ---------------------------------------------------------------------------
// Kernel G: deterministic final reductions -> loss_q, perplexity
// ---------------------------------------------------------------------------
__global__ void finalize_kernel(float* __restrict__ out)
{
    __shared__ double sh[256];
    int tid = threadIdx.x;

    double ls = 0.0;
    for (int i = tid; i < PIXELS; i += 256) ls += (double)g_lossp[i];
    sh[tid] = ls;
    __syncthreads();
    for (int o = 128; o; o >>= 1) {
        if (tid < o) sh[tid] += sh[tid + o];
        __syncthreads();
    }
    double loss = sh[0] / (double)(PIXELS * 32);
    __syncthreads();

    double ps = 0.0;
    for (int i = tid; i < NN; i += 256) {
        float u = (float)g_hist[i] * (1.0f / 8192.0f);
        ps += (double)(-u * logf(u + 1e-6f));
    }
    sh[tid] = ps;
    __syncthreads();
    for (int o = 128; o; o >>= 1) {
        if (tid < o) sh[tid] += sh[tid + o];
        __syncthreads();
    }
    if (tid == 0) {
        out[LOSS_OFF] = (float)loss;
        out[PERP_OFF] = expf((float)sh[0]);
    }
}

// ---------------------------------------------------------------------------
extern "C" void kernel_launch(void* const* d_in, const int* in_sizes, int n_in,
                              void* d_out, int out_size)
{
    const float* enc = (const float*)d_in[0];  // [8,512,32,32]
    const float* emb = (const float*)d_in[1];  // [16384,32]
    const float* pw  = (const float*)d_in[2];  // [32,512]
    const float* pb  = (const float*)d_in[3];  // [32]
    const float* ew  = (const float*)d_in[4];  // [512,32]
    const float* eb  = (const float*)d_in[5];  // [512]
    float* out = (float*)d_out;

    (void)in_sizes; (void)n_in; (void)out_size;

    const int a_smem = (FF * DD + 32 * 33 + 32) * (int)sizeof(float); // 69888
    cudaFuncSetAttribute(prep_kernel,
                         cudaFuncAttributeMaxDynamicSharedMemorySize, a_smem);

    const int c_smem = 32768;  // 2x16KB chunk buffers (x staging overlaps)
    cudaFuncSetAttribute(sims_max_kernel,
                         cudaFuncAttributeMaxDynamicSharedMemorySize, c_smem);

    prep_kernel<<<768, 256, a_smem>>>(enc, pw, pb, emb);
    sims_max_kernel<<<dim3(64, SPLITS), 256, c_smem>>>();
    flag_kernel<<<512, 256>>>();
    scan_kernel<<<296, 256>>>();
    expand_kernel<<<dim3(32, 8), 256>>>(ew, eb, out);
    finalize_kernel<<<1, 256>>>(out);
}